// round 1
// baseline (speedup 1.0000x reference)
#include <cuda_runtime.h>
#include <cuda_bf16.h>
#include <math.h>

// Problem constants
#define BATCH 2
#define DIM   128
#define HH    128
#define WW    128
#define SP    (HH*WW)        // 16384
#define HEADS 4
#define CH    32             // channels per head
#define C3    384            // 3*dim
#define KDIM  (C3*9)         // 3456  (3x3 conv K)

// Scratch (__device__ globals: allocation-free rule)
__device__ float g_W1[C3*DIM];            // 384x128 (1x1 qkv)
__device__ float g_W2[C3*C3*9];           // 384x384x3x3
__device__ float g_W3[DIM*DIM];           // 128x128 (1x1 po)
__device__ float g_y1[BATCH*C3*SP];       // after qkv conv
__device__ float g_y2[BATCH*C3*SP];       // after dw conv (q|k|v)
__device__ float g_nq[BATCH*DIM];         // q row norms (b, h*32+c)
__device__ float g_nk[BATCH*DIM];
__device__ float g_S[BATCH*HEADS*CH*CH];  // raw scores
__device__ float g_A[BATCH*HEADS*CH*CH];  // softmaxed attn
__device__ float g_ao[BATCH*DIM*SP];      // attention output

// Hamilton block tables
__constant__ int   c_comp[4][4] = {{0,1,2,3},{1,0,3,2},{2,3,0,1},{3,2,1,0}};
__constant__ float c_sgn [4][4] = {{1.f,-1.f,-1.f,-1.f},
                                   {1.f, 1.f,-1.f, 1.f},
                                   {1.f, 1.f, 1.f,-1.f},
                                   {1.f,-1.f, 1.f, 1.f}};

// ---------------------------------------------------------------------------
// Expand quaternion blocks -> full weight.  Wf[(4Bo) x (4Bi) x K]
// comp arrays are [Bo x Bi x K]
__global__ void expand_kernel(const float* __restrict__ r, const float* __restrict__ i,
                              const float* __restrict__ j, const float* __restrict__ k,
                              float* __restrict__ Wf, int Bo, int Bi, int K, int total)
{
    for (int idx = blockIdx.x*blockDim.x + threadIdx.x; idx < total;
         idx += gridDim.x*blockDim.x) {
        int kk = idx % K;
        int t  = idx / K;
        int ci = t % (4*Bi);
        int co = t / (4*Bi);
        int br = co / Bo, o  = co % Bo;
        int bc = ci / Bi, ic = ci % Bi;
        int comp = c_comp[br][bc];
        const float* src = (comp==0) ? r : (comp==1) ? i : (comp==2) ? j : k;
        Wf[idx] = c_sgn[br][bc] * src[(o*Bi + ic)*K + kk];
    }
}

// ---------------------------------------------------------------------------
// 1x1 conv as GEMM: Y[b, co, s] = sum_ci W[co,ci] X[b,ci,s] + bias[co]
// tile 64x64, 256 threads, 4x4 per thread, BK=16
__global__ __launch_bounds__(256)
void gemm1x1_kernel(const float* __restrict__ Wt, const float* __restrict__ X,
                    const float* __restrict__ bias, float* __restrict__ Y,
                    int Cout, int Cin)
{
    const int b  = blockIdx.z;
    const int n0 = blockIdx.x * 64;
    const int m0 = blockIdx.y * 64;
    const float* Xb = X + (size_t)b * Cin * SP;
    float*       Yb = Y + (size_t)b * Cout * SP;

    __shared__ float As[16][64];
    __shared__ float Bs[16][64];

    const int tid = threadIdx.x;
    const int tx  = tid % 16;     // n group
    const int ty  = tid / 16;     // m group

    float acc[4][4];
#pragma unroll
    for (int a = 0; a < 4; a++)
#pragma unroll
        for (int bb = 0; bb < 4; bb++) acc[a][bb] = 0.f;

    for (int k0 = 0; k0 < Cin; k0 += 16) {
        // load A: As[kk][m] = W[(m0+m)*Cin + k0+kk]
#pragma unroll
        for (int l = tid; l < 1024; l += 256) {
            int kk = l & 15, m = l >> 4;
            As[kk][m] = Wt[(size_t)(m0 + m)*Cin + k0 + kk];
        }
        // load B: Bs[kk][n] = X[(k0+kk)*SP + n0+n]
#pragma unroll
        for (int l = tid; l < 1024; l += 256) {
            int kk = l >> 6, n = l & 63;
            Bs[kk][n] = Xb[(size_t)(k0 + kk)*SP + n0 + n];
        }
        __syncthreads();
#pragma unroll
        for (int kk = 0; kk < 16; kk++) {
            float4 a4 = *(const float4*)&As[kk][ty*4];
            float4 b4 = *(const float4*)&Bs[kk][tx*4];
            float a[4] = {a4.x, a4.y, a4.z, a4.w};
            float bb[4] = {b4.x, b4.y, b4.z, b4.w};
#pragma unroll
            for (int im = 0; im < 4; im++)
#pragma unroll
                for (int in = 0; in < 4; in++)
                    acc[im][in] += a[im]*bb[in];
        }
        __syncthreads();
    }
#pragma unroll
    for (int im = 0; im < 4; im++) {
        float bi = bias[m0 + ty*4 + im];
#pragma unroll
        for (int in = 0; in < 4; in++)
            Yb[(size_t)(m0 + ty*4 + im)*SP + n0 + tx*4 + in] = acc[im][in] + bi;
    }
}

// ---------------------------------------------------------------------------
// 3x3 conv as implicit GEMM:  Y[b,co,y,x] = sum_{ci,ky,kx} W[co,ci,ky,kx]*X[b,ci,y+ky-1,x+kx-1]
// K = 3456.  Block: 64 co x 64 px (one image row segment).  grid.x = b*H*2, grid.y = 6
__global__ __launch_bounds__(256)
void conv3x3_kernel(const float* __restrict__ Wt, const float* __restrict__ X,
                    const float* __restrict__ bias, float* __restrict__ Y)
{
    const int pb = blockIdx.x;
    const int xt = pb & 1;
    const int y  = (pb >> 1) & 127;
    const int b  = pb >> 8;
    const int x0 = xt * 64;
    const int m0 = blockIdx.y * 64;

    const float* Xb = X + (size_t)b * C3 * SP;
    float*       Yb = Y + (size_t)b * C3 * SP;

    __shared__ float As[16][64];
    __shared__ float Bs[16][64];

    const int tid = threadIdx.x;
    const int tx  = tid % 16;
    const int ty  = tid / 16;

    float acc[4][4];
#pragma unroll
    for (int a = 0; a < 4; a++)
#pragma unroll
        for (int bb = 0; bb < 4; bb++) acc[a][bb] = 0.f;

    for (int k0 = 0; k0 < KDIM; k0 += 16) {
        // A: As[kk][m] = W[(m0+m)*KDIM + k0+kk]
#pragma unroll
        for (int l = tid; l < 1024; l += 256) {
            int kk = l & 15, m = l >> 4;
            As[kk][m] = Wt[(size_t)(m0 + m)*KDIM + k0 + kk];
        }
        // B: gather im2col
#pragma unroll
        for (int l = tid; l < 1024; l += 256) {
            int kk = l >> 6, px = l & 63;
            int gk = k0 + kk;
            int ci = gk / 9;
            int r9 = gk - ci*9;
            int ky = r9 / 3;
            int kx = r9 - ky*3;
            int iy = y + ky - 1;
            int ix = x0 + px + kx - 1;
            float v = 0.f;
            if (iy >= 0 && iy < HH && ix >= 0 && ix < WW)
                v = Xb[(size_t)ci*SP + iy*WW + ix];
            Bs[kk][px] = v;
        }
        __syncthreads();
#pragma unroll
        for (int kk = 0; kk < 16; kk++) {
            float4 a4 = *(const float4*)&As[kk][ty*4];
            float4 b4 = *(const float4*)&Bs[kk][tx*4];
            float a[4] = {a4.x, a4.y, a4.z, a4.w};
            float bb[4] = {b4.x, b4.y, b4.z, b4.w};
#pragma unroll
            for (int im = 0; im < 4; im++)
#pragma unroll
                for (int in = 0; in < 4; in++)
                    acc[im][in] += a[im]*bb[in];
        }
        __syncthreads();
    }
#pragma unroll
    for (int im = 0; im < 4; im++) {
        float bi = bias[m0 + ty*4 + im];
#pragma unroll
        for (int in = 0; in < 4; in++)
            Yb[(size_t)(m0 + ty*4 + im)*SP + y*WW + x0 + tx*4 + in] = acc[im][in] + bi;
    }
}

// ---------------------------------------------------------------------------
// Row L2 norms for q and k (clamped at eps).  grid 512, block 256.
__global__ __launch_bounds__(256)
void rownorm_kernel(const float* __restrict__ y2, float* __restrict__ nq, float* __restrict__ nk)
{
    const int r   = blockIdx.x;       // [0,512)
    const int isK = (r >= 256);
    const int rr  = r & 255;
    const int b   = rr >> 7;          // /128
    const int ch  = rr & 127;
    const float* p = y2 + (size_t)b*C3*SP + (size_t)((isK ? DIM : 0) + ch)*SP;

    float s = 0.f;
    for (int i = threadIdx.x; i < SP; i += 256) {
        float v = p[i];
        s += v*v;
    }
    // reduce
    __shared__ float red[8];
#pragma unroll
    for (int o = 16; o; o >>= 1) s += __shfl_xor_sync(~0u, s, o);
    if ((threadIdx.x & 31) == 0) red[threadIdx.x >> 5] = s;
    __syncthreads();
    if (threadIdx.x == 0) {
        float t = 0.f;
        for (int w = 0; w < 8; w++) t += red[w];
        float n = fmaxf(sqrtf(t), 1e-12f);
        if (isK) nk[b*DIM + ch] = n;
        else     nq[b*DIM + ch] = n;
    }
}

__global__ void zeroS_kernel(float* __restrict__ Sm)
{
    Sm[blockIdx.x*blockDim.x + threadIdx.x] = 0.f;
}

// scores: S[bh][c][d] += sum_{s in chunk} q[c,s]*k[d,s].  grid (8,16), block 1024
__global__ __launch_bounds__(1024)
void scores_kernel(const float* __restrict__ y2, float* __restrict__ Sm)
{
    const int bh = blockIdx.x;
    const int b  = bh >> 2, h = bh & 3;
    const int s0 = blockIdx.y * 1024;
    const int c  = threadIdx.x >> 5;
    const int d  = threadIdx.x & 31;

    const float* q = y2 + (size_t)b*C3*SP + (size_t)(h*CH)*SP;
    const float* k = q + (size_t)DIM*SP;

    __shared__ float qs[32][33];
    __shared__ float ks[32][33];

    float acc = 0.f;
    for (int ss = 0; ss < 1024; ss += 32) {
        int row = threadIdx.x >> 5, col = threadIdx.x & 31;
        qs[row][col] = q[(size_t)row*SP + s0 + ss + col];
        ks[row][col] = k[(size_t)row*SP + s0 + ss + col];
        __syncthreads();
#pragma unroll
        for (int jj = 0; jj < 32; jj++)
            acc += qs[c][jj] * ks[d][jj];
        __syncthreads();
    }
    atomicAdd(&Sm[bh*1024 + c*32 + d], acc);
}

// softmax over d (32 wide). grid 8, block 1024 (warp = row)
__global__ __launch_bounds__(1024)
void softmax_kernel(const float* __restrict__ Sm, const float* __restrict__ nq,
                    const float* __restrict__ nk, const float* __restrict__ temp,
                    float* __restrict__ Am)
{
    const int bh = blockIdx.x;
    const int b  = bh >> 2, h = bh & 3;
    const int c  = threadIdx.x >> 5;
    const int d  = threadIdx.x & 31;

    float qn = nq[b*DIM + h*CH + c];
    float kn = nk[b*DIM + h*CH + d];
    float v  = Sm[bh*1024 + c*32 + d] / (qn * kn) * temp[h];

    float m = v;
#pragma unroll
    for (int o = 16; o; o >>= 1) m = fmaxf(m, __shfl_xor_sync(~0u, m, o));
    float e = __expf(v - m);
    float s = e;
#pragma unroll
    for (int o = 16; o; o >>= 1) s += __shfl_xor_sync(~0u, s, o);
    Am[bh*1024 + c*32 + d] = e / s;
}

// out[b, h*32+c, s] = sum_d A[c,d] * v[d,s].  grid (8,64), block 256 (one s each)
__global__ __launch_bounds__(256)
void av_kernel(const float* __restrict__ y2, const float* __restrict__ Am,
               float* __restrict__ ao)
{
    const int bh = blockIdx.x;
    const int b  = bh >> 2, h = bh & 3;
    const int s  = blockIdx.y * 256 + threadIdx.x;

    __shared__ float Asm[32][32];
    for (int l = threadIdx.x; l < 1024; l += 256)
        Asm[l >> 5][l & 31] = Am[bh*1024 + l];
    __syncthreads();

    const float* v = y2 + (size_t)b*C3*SP + (size_t)(2*DIM + h*CH)*SP;
    float vr[32];
#pragma unroll
    for (int d = 0; d < 32; d++) vr[d] = v[(size_t)d*SP + s];

    float* o = ao + (size_t)b*DIM*SP + (size_t)(h*CH)*SP;
#pragma unroll
    for (int c = 0; c < 32; c++) {
        float acc = 0.f;
#pragma unroll
        for (int d = 0; d < 32; d++) acc += Asm[c][d]*vr[d];
        o[(size_t)c*SP + s] = acc;
    }
}

// ---------------------------------------------------------------------------
extern "C" void kernel_launch(void* const* d_in, const int* in_sizes, int n_in,
                              void* d_out, int out_size)
{
    const float* x      = (const float*)d_in[0];
    const float* qkv_r  = (const float*)d_in[1];
    const float* qkv_i  = (const float*)d_in[2];
    const float* qkv_j  = (const float*)d_in[3];
    const float* qkv_k  = (const float*)d_in[4];
    const float* qkv_b  = (const float*)d_in[5];
    const float* dw_r   = (const float*)d_in[6];
    const float* dw_i   = (const float*)d_in[7];
    const float* dw_j   = (const float*)d_in[8];
    const float* dw_k   = (const float*)d_in[9];
    const float* dw_b   = (const float*)d_in[10];
    const float* po_r   = (const float*)d_in[11];
    const float* po_i   = (const float*)d_in[12];
    const float* po_j   = (const float*)d_in[13];
    const float* po_k   = (const float*)d_in[14];
    const float* po_b   = (const float*)d_in[15];
    const float* temper = (const float*)d_in[16];
    float* out = (float*)d_out;

    float *W1, *W2, *W3, *y1, *y2, *nq, *nk, *Sm, *Am, *ao;
    cudaGetSymbolAddress((void**)&W1, g_W1);
    cudaGetSymbolAddress((void**)&W2, g_W2);
    cudaGetSymbolAddress((void**)&W3, g_W3);
    cudaGetSymbolAddress((void**)&y1, g_y1);
    cudaGetSymbolAddress((void**)&y2, g_y2);
    cudaGetSymbolAddress((void**)&nq, g_nq);
    cudaGetSymbolAddress((void**)&nk, g_nk);
    cudaGetSymbolAddress((void**)&Sm, g_S);
    cudaGetSymbolAddress((void**)&Am, g_A);
    cudaGetSymbolAddress((void**)&ao, g_ao);

    // 1) expand quaternion weights
    expand_kernel<<<(C3*DIM + 255)/256, 256>>>(qkv_r, qkv_i, qkv_j, qkv_k, W1, 96, 32, 1, C3*DIM);
    expand_kernel<<<(C3*C3*9 + 255)/256, 256>>>(dw_r, dw_i, dw_j, dw_k, W2, 96, 96, 9, C3*C3*9);
    expand_kernel<<<(DIM*DIM + 255)/256, 256>>>(po_r, po_i, po_j, po_k, W3, 32, 32, 1, DIM*DIM);

    // 2) qkv 1x1 conv: y1 = W1 @ x + b
    gemm1x1_kernel<<<dim3(SP/64, C3/64, BATCH), 256>>>(W1, x, qkv_b, y1, C3, DIM);

    // 3) dw 3x3 conv: y2 = conv3x3(y1) + b
    conv3x3_kernel<<<dim3(BATCH*HH*2, C3/64), 256>>>(W2, y1, dw_b, y2);

    // 4) q/k row norms
    rownorm_kernel<<<512, 256>>>(y2, nq, nk);

    // 5) raw scores (zero + atomic accumulate over spatial chunks)
    zeroS_kernel<<<8, 1024>>>(Sm);
    scores_kernel<<<dim3(8, 16), 1024>>>(y2, Sm);

    // 6) normalize + temperature + softmax
    softmax_kernel<<<8, 1024>>>(Sm, nq, nk, temper, Am);

    // 7) attention output
    av_kernel<<<dim3(8, SP/256), 256>>>(y2, Am, ao);

    // 8) po 1x1 conv -> d_out
    gemm1x1_kernel<<<dim3(SP/64, DIM/64, BATCH), 256>>>(W3, ao, po_b, out, DIM, DIM);
}

// round 3
// speedup vs baseline: 3.6409x; 3.6409x over previous
#include <cuda_runtime.h>
#include <cuda_bf16.h>
#include <cstdint>
#include <math.h>

// Problem constants
#define BATCH 2
#define DIM   128
#define HH    128
#define WW    128
#define SP    (HH*WW)        // 16384
#define HEADS 4
#define CH    32
#define C3    384
#define KDIM  (C3*9)         // 3456
#define KC    108            // 3456/32 k-chunks
#define PXR   130            // padded rows (H + 2)
#define PXC   132            // padded cols

// smem layout for conv kernel (per stage)
#define AOFF_LO 10240
#define BOFF    20480
#define BOFF_LO 29184
#define STAGE   37888
#define CV_SMEM (2*STAGE)    // 75776

// ---------------------------------------------------------------------------
// Scratch (__device__ globals: allocation-free rule)
__device__ float g_W1[C3*DIM];
__device__ float g_W3[DIM*DIM];
__device__ float g_y1[BATCH*C3*SP];
__device__ float g_y2[BATCH*C3*SP];
__device__ __nv_bfloat16 g_Whi[KC*C3*40];      // pre-tiled weights (hi), rows padded to 40
__device__ __nv_bfloat16 g_Wlo[KC*C3*40];      // (lo)
__device__ uint32_t g_Xpk[BATCH*C3*PXR*PXC];   // padded input, packed (hi | lo<<16)
__device__ float g_nq[BATCH*DIM];
__device__ float g_nk[BATCH*DIM];
__device__ float g_S[BATCH*HEADS*CH*CH];
__device__ float g_A[BATCH*HEADS*CH*CH];
__device__ float g_ao[BATCH*DIM*SP];

// Hamilton block tables
__constant__ int   c_comp[4][4] = {{0,1,2,3},{1,0,3,2},{2,3,0,1},{3,2,1,0}};
__constant__ float c_sgn [4][4] = {{1.f,-1.f,-1.f,-1.f},
                                   {1.f, 1.f,-1.f, 1.f},
                                   {1.f, 1.f, 1.f,-1.f},
                                   {1.f,-1.f, 1.f, 1.f}};

// ---------------------------------------------------------------------------
__device__ __forceinline__ uint32_t smem_to_u32(const void* p) {
    uint32_t a;
    asm("{ .reg .u64 t; cvta.to.shared.u64 t, %1; cvt.u32.u64 %0, t; }" : "=r"(a) : "l"(p));
    return a;
}

__device__ __forceinline__ void cp16(uint32_t dst, const void* src) {
    asm volatile("cp.async.cg.shared.global [%0], [%1], 16;" :: "r"(dst), "l"(src) : "memory");
}
#define CP_COMMIT() asm volatile("cp.async.commit_group;" ::: "memory")
#define CP_WAIT0()  asm volatile("cp.async.wait_group 0;" ::: "memory")

__device__ __forceinline__ void ldm_x4(uint32_t* r, uint32_t addr) {
    asm volatile("ldmatrix.sync.aligned.m8n8.x4.shared.b16 {%0,%1,%2,%3}, [%4];"
        : "=r"(r[0]), "=r"(r[1]), "=r"(r[2]), "=r"(r[3]) : "r"(addr));
}
__device__ __forceinline__ void ldm_x4_t(uint32_t* r, uint32_t addr) {
    asm volatile("ldmatrix.sync.aligned.m8n8.x4.trans.shared.b16 {%0,%1,%2,%3}, [%4];"
        : "=r"(r[0]), "=r"(r[1]), "=r"(r[2]), "=r"(r[3]) : "r"(addr));
}
__device__ __forceinline__ void mma16816(float* c, const uint32_t* a, const uint32_t* b) {
    asm volatile("mma.sync.aligned.m16n8k16.row.col.f32.bf16.bf16.f32 "
        "{%0,%1,%2,%3}, {%4,%5,%6,%7}, {%8,%9}, {%0,%1,%2,%3};"
        : "+f"(c[0]), "+f"(c[1]), "+f"(c[2]), "+f"(c[3])
        : "r"(a[0]), "r"(a[1]), "r"(a[2]), "r"(a[3]), "r"(b[0]), "r"(b[1]));
}

// ---------------------------------------------------------------------------
// Expand quaternion blocks -> full fp32 weight (for 1x1 convs)
__global__ void expand_kernel(const float* __restrict__ r, const float* __restrict__ i,
                              const float* __restrict__ j, const float* __restrict__ k,
                              float* __restrict__ Wf, int Bo, int Bi, int K, int total)
{
    for (int idx = blockIdx.x*blockDim.x + threadIdx.x; idx < total;
         idx += gridDim.x*blockDim.x) {
        int kk = idx % K;
        int t  = idx / K;
        int ci = t % (4*Bi);
        int co = t / (4*Bi);
        int br = co / Bo, o  = co % Bo;
        int bc = ci / Bi, ic = ci % Bi;
        int comp = c_comp[br][bc];
        const float* src = (comp==0) ? r : (comp==1) ? i : (comp==2) ? j : k;
        Wf[idx] = c_sgn[br][bc] * src[(o*Bi + ic)*K + kk];
    }
}

// Expand + split dw weights into chunked tile layout [chunk][co][40]
__global__ void expandsplitA_kernel(const float* __restrict__ r, const float* __restrict__ i,
                                    const float* __restrict__ j, const float* __restrict__ k,
                                    __nv_bfloat16* __restrict__ Whi, __nv_bfloat16* __restrict__ Wlo)
{
    int idx = blockIdx.x*blockDim.x + threadIdx.x;
    if (idx >= C3*KDIM) return;
    int kidx = idx % KDIM;
    int co   = idx / KDIM;
    int ci = kidx / 9, r9 = kidx % 9;
    int br = co / 96, o = co % 96;
    int bc = ci / 96, ic = ci % 96;
    int comp = c_comp[br][bc];
    const float* src = (comp==0) ? r : (comp==1) ? i : (comp==2) ? j : k;
    float v = c_sgn[br][bc] * src[(o*96 + ic)*9 + r9];

    __nv_bfloat16 hi = __float2bfloat16(v);
    __nv_bfloat16 lo = __float2bfloat16(v - __bfloat162float(hi));

    int chunk = kidx >> 5;
    int kk    = kidx & 31;
    size_t dst = ((size_t)chunk*C3 + co)*40 + kk;
    Whi[dst] = hi;
    Wlo[dst] = lo;
}

// Split y1 -> padded packed (hi|lo) bf16 pairs
__global__ void splitX_kernel(const float* __restrict__ y1, uint32_t* __restrict__ Xpk)
{
    int idx = blockIdx.x*blockDim.x + threadIdx.x;
    const int TOT = BATCH*C3*PXR*PXC;
    if (idx >= TOT) return;
    int col = idx % PXC;
    int t   = idx / PXC;
    int row = t % PXR;
    int bc  = t / PXR;
    int y = row - 1, x = col - 1;
    float v = 0.f;
    if (y >= 0 && y < HH && x >= 0 && x < WW)
        v = y1[(size_t)bc*SP + y*WW + x];
    __nv_bfloat16 hi = __float2bfloat16(v);
    __nv_bfloat16 lo = __float2bfloat16(v - __bfloat162float(hi));
    uint32_t u = (uint32_t)__bfloat16_as_ushort(hi) |
                 ((uint32_t)__bfloat16_as_ushort(lo) << 16);
    Xpk[idx] = u;
}

// ---------------------------------------------------------------------------
// 3x3 conv as implicit GEMM on mma.sync (bf16 split, 3 passes, fp32 acc)
// grid (256 = b*128 rows, 3 = co blocks of 128), 256 threads (8 warps, 2x4)
__global__ __launch_bounds__(256)
void conv3x3_mma_kernel(const __nv_bfloat16* __restrict__ Whi,
                        const __nv_bfloat16* __restrict__ Wlo,
                        const uint32_t* __restrict__ Xpk,
                        const float* __restrict__ bias, float* __restrict__ Y)
{
    extern __shared__ char smc[];
    const uint32_t sb = smem_to_u32(smc);
    const int tid = threadIdx.x, lane = tid & 31, wid = tid >> 5;
    const int bx = blockIdx.x;
    const int b  = bx >> 7;
    const int y  = bx & 127;
    const int co0 = blockIdx.y * 128;
    const int warp_m = wid >> 2;      // 0..1
    const int warp_n = wid & 3;       // 0..3

    float acc[4][4][4];
#pragma unroll
    for (int a = 0; a < 4; a++)
#pragma unroll
        for (int c = 0; c < 4; c++)
#pragma unroll
            for (int e = 0; e < 4; e++) acc[a][c][e] = 0.f;

    const int kb  = tid >> 3;   // k index in chunk (0..31)
    const int pxb = tid & 7;    // px base, stride 8

    // ---- prologue: stage chunk 0 into stage 0 ----
    {
        const char* sh = (const char*)Whi + (size_t)co0*80;
        const char* sl = (const char*)Wlo + (size_t)co0*80;
        for (int t2 = tid; t2 < 640; t2 += 256) {
            cp16(sb + t2*16,           sh + t2*16);
            cp16(sb + AOFF_LO + t2*16, sl + t2*16);
        }
        CP_COMMIT();
        int kg = kb;
        int ci = kg/9; int r9 = kg - ci*9; int ky = r9/3; int kx = r9 - ky*3;
        const uint32_t* src = Xpk + (size_t)((b*C3+ci)*PXR + (y+ky))*PXC + kx + pxb;
        uint32_t g[16];
#pragma unroll
        for (int i2 = 0; i2 < 16; i2++) g[i2] = src[8*i2];
        int ro = kb*136 + pxb;
#pragma unroll
        for (int i2 = 0; i2 < 16; i2++) {
            *(unsigned short*)(smc + BOFF    + (ro + 8*i2)*2) = (unsigned short)(g[i2] & 0xffff);
            *(unsigned short*)(smc + BOFF_LO + (ro + 8*i2)*2) = (unsigned short)(g[i2] >> 16);
        }
        CP_WAIT0();
        __syncthreads();
    }

    const int quad = lane >> 3, qi = lane & 7;

    for (int it = 0; it < KC; it++) {
        const int s = it & 1;
        const uint32_t stage  = sb + s*STAGE;
        const uint32_t nstoff = (s^1)*STAGE;
        const bool hasNext = (it + 1) < KC;

        uint32_t g[16];
        if (hasNext) {
            // A tiles for next chunk via cp.async (contiguous 10240B per split)
            const char* sh = (const char*)Whi + ((size_t)(it+1)*C3 + co0)*80;
            const char* sl = (const char*)Wlo + ((size_t)(it+1)*C3 + co0)*80;
            for (int t2 = tid; t2 < 640; t2 += 256) {
                cp16(sb + nstoff + t2*16,           sh + t2*16);
                cp16(sb + nstoff + AOFF_LO + t2*16, sl + t2*16);
            }
            CP_COMMIT();
            // B gather (next chunk) into regs; latency hides under mma below
            int kg = (it+1)*32 + kb;
            int ci = kg/9; int r9 = kg - ci*9; int ky = r9/3; int kx = r9 - ky*3;
            const uint32_t* src = Xpk + (size_t)((b*C3+ci)*PXR + (y+ky))*PXC + kx + pxb;
#pragma unroll
            for (int i2 = 0; i2 < 16; i2++) g[i2] = src[8*i2];
        }

        // ---- mma on current stage ----
#pragma unroll
        for (int ks = 0; ks < 2; ks++) {
            const int k0 = ks*16;
            uint32_t Ah[4][4], Al[4][4], Bh[4][2], Bl[4][2];
            const int arow = warp_m*64 + (quad&1)*8 + qi;
            const int acol = k0 + (quad>>1)*8;
#pragma unroll
            for (int mf = 0; mf < 4; mf++) {
                uint32_t ad = stage + (uint32_t)((arow + mf*16)*40 + acol)*2;
                ldm_x4(Ah[mf], ad);
                ldm_x4(Al[mf], ad + AOFF_LO);
            }
            const int brow = k0 + (quad&1)*8 + qi;
#pragma unroll
            for (int p2 = 0; p2 < 2; p2++) {
                const int n0 = warp_n*32 + p2*16 + (quad>>1)*8;
                uint32_t bd = stage + BOFF + (uint32_t)(brow*136 + n0)*2;
                uint32_t r4[4];
                ldm_x4_t(r4, bd);
                Bh[p2*2][0]=r4[0]; Bh[p2*2][1]=r4[1]; Bh[p2*2+1][0]=r4[2]; Bh[p2*2+1][1]=r4[3];
                ldm_x4_t(r4, bd + (BOFF_LO - BOFF));
                Bl[p2*2][0]=r4[0]; Bl[p2*2][1]=r4[1]; Bl[p2*2+1][0]=r4[2]; Bl[p2*2+1][1]=r4[3];
            }
#pragma unroll
            for (int mf = 0; mf < 4; mf++)
#pragma unroll
                for (int nf = 0; nf < 4; nf++) {
                    mma16816(acc[mf][nf], Ah[mf], Bh[nf]);
                    mma16816(acc[mf][nf], Ah[mf], Bl[nf]);
                    mma16816(acc[mf][nf], Al[mf], Bh[nf]);
                }
        }

        if (hasNext) {
            int ro = kb*136 + pxb;
#pragma unroll
            for (int i2 = 0; i2 < 16; i2++) {
                *(unsigned short*)(smc + nstoff + BOFF    + (ro + 8*i2)*2) = (unsigned short)(g[i2] & 0xffff);
                *(unsigned short*)(smc + nstoff + BOFF_LO + (ro + 8*i2)*2) = (unsigned short)(g[i2] >> 16);
            }
        }
        CP_WAIT0();
        __syncthreads();
    }

    // ---- epilogue ----
    const int r = lane >> 2, cpx = (lane & 3)*2;
#pragma unroll
    for (int mf = 0; mf < 4; mf++) {
        int coA = co0 + warp_m*64 + mf*16 + r;
        float b0 = bias[coA], b1 = bias[coA + 8];
#pragma unroll
        for (int nf = 0; nf < 4; nf++) {
            int px = warp_n*32 + nf*8 + cpx;
            float2 v0 = { acc[mf][nf][0] + b0, acc[mf][nf][1] + b0 };
            float2 v1 = { acc[mf][nf][2] + b1, acc[mf][nf][3] + b1 };
            *(float2*)&Y[((size_t)(b*C3 + coA    ))*SP + y*WW + px] = v0;
            *(float2*)&Y[((size_t)(b*C3 + coA + 8))*SP + y*WW + px] = v1;
        }
    }
}

// ---------------------------------------------------------------------------
// 1x1 conv as GEMM (fp32 SIMT)
__global__ __launch_bounds__(256)
void gemm1x1_kernel(const float* __restrict__ Wt, const float* __restrict__ X,
                    const float* __restrict__ bias, float* __restrict__ Y,
                    int Cout, int Cin)
{
    const int b  = blockIdx.z;
    const int n0 = blockIdx.x * 64;
    const int m0 = blockIdx.y * 64;
    const float* Xb = X + (size_t)b * Cin * SP;
    float*       Yb = Y + (size_t)b * Cout * SP;

    __shared__ float As[16][64];
    __shared__ float Bs[16][64];

    const int tid = threadIdx.x;
    const int tx  = tid % 16;
    const int ty  = tid / 16;

    float acc[4][4];
#pragma unroll
    for (int a = 0; a < 4; a++)
#pragma unroll
        for (int bb = 0; bb < 4; bb++) acc[a][bb] = 0.f;

    for (int k0 = 0; k0 < Cin; k0 += 16) {
#pragma unroll
        for (int l = tid; l < 1024; l += 256) {
            int kk = l & 15, m = l >> 4;
            As[kk][m] = Wt[(size_t)(m0 + m)*Cin + k0 + kk];
        }
#pragma unroll
        for (int l = tid; l < 1024; l += 256) {
            int kk = l >> 6, n = l & 63;
            Bs[kk][n] = Xb[(size_t)(k0 + kk)*SP + n0 + n];
        }
        __syncthreads();
#pragma unroll
        for (int kk = 0; kk < 16; kk++) {
            float4 a4 = *(const float4*)&As[kk][ty*4];
            float4 b4 = *(const float4*)&Bs[kk][tx*4];
            float a[4] = {a4.x, a4.y, a4.z, a4.w};
            float bb[4] = {b4.x, b4.y, b4.z, b4.w};
#pragma unroll
            for (int im = 0; im < 4; im++)
#pragma unroll
                for (int in = 0; in < 4; in++)
                    acc[im][in] += a[im]*bb[in];
        }
        __syncthreads();
    }
#pragma unroll
    for (int im = 0; im < 4; im++) {
        float bi = bias[m0 + ty*4 + im];
#pragma unroll
        for (int in = 0; in < 4; in++)
            Yb[(size_t)(m0 + ty*4 + im)*SP + n0 + tx*4 + in] = acc[im][in] + bi;
    }
}

// ---------------------------------------------------------------------------
__global__ __launch_bounds__(256)
void rownorm_kernel(const float* __restrict__ y2, float* __restrict__ nq, float* __restrict__ nk)
{
    const int r   = blockIdx.x;
    const int isK = (r >= 256);
    const int rr  = r & 255;
    const int b   = rr >> 7;
    const int ch  = rr & 127;
    const float* p = y2 + (size_t)b*C3*SP + (size_t)((isK ? DIM : 0) + ch)*SP;

    float s = 0.f;
    for (int i = threadIdx.x; i < SP; i += 256) {
        float v = p[i];
        s += v*v;
    }
    __shared__ float red[8];
#pragma unroll
    for (int o = 16; o; o >>= 1) s += __shfl_xor_sync(~0u, s, o);
    if ((threadIdx.x & 31) == 0) red[threadIdx.x >> 5] = s;
    __syncthreads();
    if (threadIdx.x == 0) {
        float t = 0.f;
        for (int w = 0; w < 8; w++) t += red[w];
        float n = fmaxf(sqrtf(t), 1e-12f);
        if (isK) nk[b*DIM + ch] = n;
        else     nq[b*DIM + ch] = n;
    }
}

__global__ void zeroS_kernel(float* __restrict__ Sm)
{
    Sm[blockIdx.x*blockDim.x + threadIdx.x] = 0.f;
}

__global__ __launch_bounds__(1024)
void scores_kernel(const float* __restrict__ y2, float* __restrict__ Sm)
{
    const int bh = blockIdx.x;
    const int b  = bh >> 2, h = bh & 3;
    const int s0 = blockIdx.y * 1024;
    const int c  = threadIdx.x >> 5;
    const int d  = threadIdx.x & 31;

    const float* q = y2 + (size_t)b*C3*SP + (size_t)(h*CH)*SP;
    const float* k = q + (size_t)DIM*SP;

    __shared__ float qs[32][33];
    __shared__ float ks[32][33];

    float acc = 0.f;
    for (int ss = 0; ss < 1024; ss += 32) {
        int row = threadIdx.x >> 5, col = threadIdx.x & 31;
        qs[row][col] = q[(size_t)row*SP + s0 + ss + col];
        ks[row][col] = k[(size_t)row*SP + s0 + ss + col];
        __syncthreads();
#pragma unroll
        for (int jj = 0; jj < 32; jj++)
            acc += qs[c][jj] * ks[d][jj];
        __syncthreads();
    }
    atomicAdd(&Sm[bh*1024 + c*32 + d], acc);
}

__global__ __launch_bounds__(1024)
void softmax_kernel(const float* __restrict__ Sm, const float* __restrict__ nq,
                    const float* __restrict__ nk, const float* __restrict__ temp,
                    float* __restrict__ Am)
{
    const int bh = blockIdx.x;
    const int b  = bh >> 2, h = bh & 3;
    const int c  = threadIdx.x >> 5;
    const int d  = threadIdx.x & 31;

    float qn = nq[b*DIM + h*CH + c];
    float kn = nk[b*DIM + h*CH + d];
    float v  = Sm[bh*1024 + c*32 + d] / (qn * kn) * temp[h];

    float m = v;
#pragma unroll
    for (int o = 16; o; o >>= 1) m = fmaxf(m, __shfl_xor_sync(~0u, m, o));
    float e = __expf(v - m);
    float s = e;
#pragma unroll
    for (int o = 16; o; o >>= 1) s += __shfl_xor_sync(~0u, s, o);
    Am[bh*1024 + c*32 + d] = e / s;
}

__global__ __launch_bounds__(256)
void av_kernel(const float* __restrict__ y2, const float* __restrict__ Am,
               float* __restrict__ ao)
{
    const int bh = blockIdx.x;
    const int b  = bh >> 2, h = bh & 3;
    const int s  = blockIdx.y * 256 + threadIdx.x;

    __shared__ float Asm[32][32];
    for (int l = threadIdx.x; l < 1024; l += 256)
        Asm[l >> 5][l & 31] = Am[bh*1024 + l];
    __syncthreads();

    const float* v = y2 + (size_t)b*C3*SP + (size_t)(2*DIM + h*CH)*SP;
    float vr[32];
#pragma unroll
    for (int d = 0; d < 32; d++) vr[d] = v[(size_t)d*SP + s];

    float* o = ao + (size_t)b*DIM*SP + (size_t)(h*CH)*SP;
#pragma unroll
    for (int c = 0; c < 32; c++) {
        float acc = 0.f;
#pragma unroll
        for (int d = 0; d < 32; d++) acc += Asm[c][d]*vr[d];
        o[(size_t)c*SP + s] = acc;
    }
}

// ---------------------------------------------------------------------------
extern "C" void kernel_launch(void* const* d_in, const int* in_sizes, int n_in,
                              void* d_out, int out_size)
{
    const float* x      = (const float*)d_in[0];
    const float* qkv_r  = (const float*)d_in[1];
    const float* qkv_i  = (const float*)d_in[2];
    const float* qkv_j  = (const float*)d_in[3];
    const float* qkv_k  = (const float*)d_in[4];
    const float* qkv_b  = (const float*)d_in[5];
    const float* dw_r   = (const float*)d_in[6];
    const float* dw_i   = (const float*)d_in[7];
    const float* dw_j   = (const float*)d_in[8];
    const float* dw_k   = (const float*)d_in[9];
    const float* dw_b   = (const float*)d_in[10];
    const float* po_r   = (const float*)d_in[11];
    const float* po_i   = (const float*)d_in[12];
    const float* po_j   = (const float*)d_in[13];
    const float* po_k   = (const float*)d_in[14];
    const float* po_b   = (const float*)d_in[15];
    const float* temper = (const float*)d_in[16];
    float* out = (float*)d_out;

    float *W1, *W3, *y1, *y2, *nq, *nk, *Sm, *Am, *ao;
    __nv_bfloat16 *Whi, *Wlo;
    uint32_t *Xpk;
    cudaGetSymbolAddress((void**)&W1, g_W1);
    cudaGetSymbolAddress((void**)&W3, g_W3);
    cudaGetSymbolAddress((void**)&y1, g_y1);
    cudaGetSymbolAddress((void**)&y2, g_y2);
    cudaGetSymbolAddress((void**)&nq, g_nq);
    cudaGetSymbolAddress((void**)&nk, g_nk);
    cudaGetSymbolAddress((void**)&Sm, g_S);
    cudaGetSymbolAddress((void**)&Am, g_A);
    cudaGetSymbolAddress((void**)&ao, g_ao);
    cudaGetSymbolAddress((void**)&Whi, g_Whi);
    cudaGetSymbolAddress((void**)&Wlo, g_Wlo);
    cudaGetSymbolAddress((void**)&Xpk, g_Xpk);

    cudaFuncSetAttribute(conv3x3_mma_kernel,
                         cudaFuncAttributeMaxDynamicSharedMemorySize, CV_SMEM);

    // 1) expand 1x1 quaternion weights (fp32)
    expand_kernel<<<(C3*DIM + 255)/256, 256>>>(qkv_r, qkv_i, qkv_j, qkv_k, W1, 96, 32, 1, C3*DIM);
    expand_kernel<<<(DIM*DIM + 255)/256, 256>>>(po_r, po_i, po_j, po_k, W3, 32, 32, 1, DIM*DIM);

    // 2) qkv 1x1 conv
    gemm1x1_kernel<<<dim3(SP/64, C3/64, BATCH), 256>>>(W1, x, qkv_b, y1, C3, DIM);

    // 3) prep: expand+split dw weights (tiled), split+pad+pack input
    expandsplitA_kernel<<<(C3*KDIM + 255)/256, 256>>>(dw_r, dw_i, dw_j, dw_k, Whi, Wlo);
    splitX_kernel<<<(BATCH*C3*PXR*PXC + 255)/256, 256>>>(y1, Xpk);

    // 4) 3x3 conv on mma.sync tensor cores
    conv3x3_mma_kernel<<<dim3(BATCH*HH, 3), 256, CV_SMEM>>>(Whi, Wlo, Xpk, dw_b, y2);

    // 5) attention
    rownorm_kernel<<<512, 256>>>(y2, nq, nk);
    zeroS_kernel<<<8, 1024>>>(Sm);
    scores_kernel<<<dim3(8, 16), 1024>>>(y2, Sm);
    softmax_kernel<<<8, 1024>>>(Sm, nq, nk, temper, Am);
    av_kernel<<<dim3(8, SP/256), 256>>>(y2, Am, ao);

    // 6) po 1x1 conv -> out
    gemm1x1_kernel<<<dim3(SP/64, DIM/64, BATCH), 256>>>(W3, ao, po_b, out, DIM, DIM);
}

// round 4
// speedup vs baseline: 5.0699x; 1.3925x over previous
#include <cuda_runtime.h>
#include <cuda_fp16.h>
#include <cstdint>
#include <math.h>

// Problem constants
#define BATCH 2
#define DIM   128
#define HH    128
#define WW    128
#define SP    (HH*WW)        // 16384
#define HEADS 4
#define CH    32
#define C3    384
#define PXR   130            // padded rows
#define PXC   132            // padded cols

// ---------------------------------------------------------------------------
// Scratch (__device__ globals: allocation-free rule)
__device__ __half  g_Wq_hi[4*C3*40];          // qkv weights chunked [chunk][co][40]
__device__ __half  g_Wq_lo[4*C3*40];
__device__ __half  g_Wd_hi[108*C3*40];        // dw weights (hi only, 2-pass)
__device__ __half  g_Wp_hi[4*DIM*40];         // po weights
__device__ __half  g_Wp_lo[4*DIM*40];
__device__ uint32_t g_Xq [BATCH*DIM*SP];      // packed input x (fp16 hi|lo)
__device__ uint32_t g_Xpk[BATCH*C3*PXR*PXC];  // padded packed qkv output
__device__ uint32_t g_aopk[BATCH*DIM*SP];     // packed attention output
__device__ float g_y2[BATCH*C3*SP];           // dw conv output (q|k|v), fp32
__device__ float g_nq[BATCH*DIM];
__device__ float g_nk[BATCH*DIM];
__device__ float g_S[BATCH*HEADS*CH*CH];
__device__ float g_A[BATCH*HEADS*CH*CH];

// Hamilton block tables
__constant__ int   c_comp[4][4] = {{0,1,2,3},{1,0,3,2},{2,3,0,1},{3,2,1,0}};
__constant__ float c_sgn [4][4] = {{1.f,-1.f,-1.f,-1.f},
                                   {1.f, 1.f,-1.f, 1.f},
                                   {1.f, 1.f, 1.f,-1.f},
                                   {1.f,-1.f, 1.f, 1.f}};

// ---------------------------------------------------------------------------
__device__ __forceinline__ uint32_t smem_to_u32(const void* p) {
    uint32_t a;
    asm("{ .reg .u64 t; cvta.to.shared.u64 t, %1; cvt.u32.u64 %0, t; }" : "=r"(a) : "l"(p));
    return a;
}
__device__ __forceinline__ void cp16(uint32_t dst, const void* src) {
    asm volatile("cp.async.cg.shared.global [%0], [%1], 16;" :: "r"(dst), "l"(src) : "memory");
}
#define CP_COMMIT() asm volatile("cp.async.commit_group;" ::: "memory")
#define CP_WAIT0()  asm volatile("cp.async.wait_group 0;" ::: "memory")

__device__ __forceinline__ void ldm_x4(uint32_t* r, uint32_t addr) {
    asm volatile("ldmatrix.sync.aligned.m8n8.x4.shared.b16 {%0,%1,%2,%3}, [%4];"
        : "=r"(r[0]), "=r"(r[1]), "=r"(r[2]), "=r"(r[3]) : "r"(addr));
}
__device__ __forceinline__ void ldm_x4_t(uint32_t* r, uint32_t addr) {
    asm volatile("ldmatrix.sync.aligned.m8n8.x4.trans.shared.b16 {%0,%1,%2,%3}, [%4];"
        : "=r"(r[0]), "=r"(r[1]), "=r"(r[2]), "=r"(r[3]) : "r"(addr));
}
__device__ __forceinline__ void mma16816(float* c, const uint32_t* a, const uint32_t* b) {
    asm volatile("mma.sync.aligned.m16n8k16.row.col.f32.f16.f16.f32 "
        "{%0,%1,%2,%3}, {%4,%5,%6,%7}, {%8,%9}, {%0,%1,%2,%3};"
        : "+f"(c[0]), "+f"(c[1]), "+f"(c[2]), "+f"(c[3])
        : "r"(a[0]), "r"(a[1]), "r"(a[2]), "r"(b[0]), "r"(b[1]), "r"(a[3]) : );
}

// NOTE: operand order must be a0..a3 then b0,b1 — write it correctly:
__device__ __forceinline__ void mma16816f(float* c, const uint32_t* a, const uint32_t* b) {
    asm volatile("mma.sync.aligned.m16n8k16.row.col.f32.f16.f16.f32 "
        "{%0,%1,%2,%3}, {%4,%5,%6,%7}, {%8,%9}, {%0,%1,%2,%3};"
        : "+f"(c[0]), "+f"(c[1]), "+f"(c[2]), "+f"(c[3])
        : "r"(a[0]), "r"(a[1]), "r"(a[2]), "r"(a[3]), "r"(b[0]), "r"(b[1]));
}

__device__ __forceinline__ uint32_t packhl(float v) {
    __half h = __float2half(v);
    __half l = __float2half(v - __half2float(h));
    return (uint32_t)__half_as_ushort(h) | ((uint32_t)__half_as_ushort(l) << 16);
}

// ---------------------------------------------------------------------------
// Hamilton expand + fp16 split + chunked tiling: dst[(chunk*COUT + co)*40 + kk]
__global__ void prepW_kernel(const float* __restrict__ r, const float* __restrict__ i,
                             const float* __restrict__ j, const float* __restrict__ k,
                             __half* __restrict__ Whi, __half* __restrict__ Wlo,
                             int Bo, int Bi, int K9, int writeLo)
{
    int total = 16*Bo*Bi*K9;
    int idx = blockIdx.x*blockDim.x + threadIdx.x;
    if (idx >= total) return;
    int KD = 4*Bi*K9;
    int co = idx / KD;
    int kidx = idx % KD;
    int ci = kidx / K9, r9 = kidx % K9;
    int br = co / Bo, o = co % Bo;
    int bc = ci / Bi, ic = ci % Bi;
    int comp = c_comp[br][bc];
    const float* src = (comp==0) ? r : (comp==1) ? i : (comp==2) ? j : k;
    float v = c_sgn[br][bc] * src[(o*Bi + ic)*K9 + r9];
    __half h = __float2half(v);
    int chunk = kidx >> 5, kk = kidx & 31;
    size_t dst = ((size_t)chunk*(4*Bo) + co)*40 + kk;
    Whi[dst] = h;
    if (writeLo) Wlo[dst] = __float2half(v - __half2float(h));
}

// Pack raw input x -> fp16 hi|lo u32
__global__ void packX_kernel(const float* __restrict__ x, uint32_t* __restrict__ Xq)
{
    int idx = blockIdx.x*blockDim.x + threadIdx.x;
    if (idx < BATCH*DIM*SP) Xq[idx] = packhl(x[idx]);
}

// Zero the border cells of the padded packed buffer
__global__ void borderzero_kernel(uint32_t* __restrict__ Xpk)
{
    int idx = blockIdx.x*blockDim.x + threadIdx.x;
    const int TOT = BATCH*C3*PXR*PXC;
    if (idx >= TOT) return;
    int col = idx % PXC;
    int row = (idx / PXC) % PXR;
    if (row == 0 || row == PXR-1 || col == 0 || col >= WW+1)
        Xpk[idx] = 0u;
}

// ---------------------------------------------------------------------------
// Unified implicit-GEMM conv on mma.sync (fp16, fp32 accum)
// CTA: 128 co x 128 px (one image row), 8 warps (2x4), K in chunks of 32.
// P3: 3-pass (Ah*Bh + Ah*Bl + Al*Bh); else 2-pass (Ah*Bh + Ah*Bl).
// OPACK: write padded packed fp16 (qkv), else fp32.
template<int CIN, int KSZ, int COUT, bool P3, bool OPACK>
__global__ __launch_bounds__(256)
void convmma_kernel(const __half* __restrict__ Whi, const __half* __restrict__ Wlo,
                    const uint32_t* __restrict__ Xin, const float* __restrict__ bias,
                    float* __restrict__ Yf, uint32_t* __restrict__ Ypk,
                    int PR, int PC)
{
    constexpr int K   = CIN*KSZ*KSZ;
    constexpr int KCn = K/32;
    constexpr int S_AL = 10240;                    // A-lo offset (P3 only)
    constexpr int S_BH = P3 ? 20480 : 10240;
    constexpr int S_BL = S_BH + 8704;
    constexpr int S_SZ = S_BL + 8704;

    extern __shared__ char smc[];
    const uint32_t sb = smem_to_u32(smc);
    const int tid = threadIdx.x, lane = tid & 31, wid = tid >> 5;
    const int bx = blockIdx.x;
    const int b  = bx >> 7;
    const int y  = bx & 127;
    const int co0 = blockIdx.y * 128;
    const int warp_m = wid >> 2;
    const int warp_n = wid & 3;

    float acc[4][4][4];
#pragma unroll
    for (int a = 0; a < 4; a++)
#pragma unroll
        for (int c = 0; c < 4; c++)
#pragma unroll
            for (int e = 0; e < 4; e++) acc[a][c][e] = 0.f;

    const int kb  = tid >> 3;   // k within chunk (0..31)
    const int pxb = tid & 7;    // px base

    // ---- prologue: stage chunk 0 ----
    {
        const char* sh = (const char*)(Whi + (size_t)co0*40);
        for (int t2 = tid; t2 < 640; t2 += 256) cp16(sb + t2*16, sh + t2*16);
        if (P3) {
            const char* sl = (const char*)(Wlo + (size_t)co0*40);
            for (int t2 = tid; t2 < 640; t2 += 256) cp16(sb + S_AL + t2*16, sl + t2*16);
        }
        CP_COMMIT();
        int kg = kb;
        int ci, ky, kx;
        if (KSZ == 3) { ci = kg/9; int r9 = kg - ci*9; ky = r9/3; kx = r9 - ky*3; }
        else          { ci = kg; ky = 0; kx = 0; }
        const uint32_t* src = Xin + ((size_t)(b*CIN + ci)*PR + (y + ky))*PC + kx + pxb;
        uint32_t g[16];
#pragma unroll
        for (int i2 = 0; i2 < 16; i2++) g[i2] = src[8*i2];
        int ro = kb*136 + pxb;
#pragma unroll
        for (int i2 = 0; i2 < 16; i2++) {
            *(unsigned short*)(smc + S_BH + (ro + 8*i2)*2) = (unsigned short)(g[i2] & 0xffff);
            *(unsigned short*)(smc + S_BL + (ro + 8*i2)*2) = (unsigned short)(g[i2] >> 16);
        }
        CP_WAIT0();
        __syncthreads();
    }

    const int quad = lane >> 3, qi = lane & 7;

    for (int it = 0; it < KCn; it++) {
        const int s = it & 1;
        const uint32_t stage  = sb + s*S_SZ;
        const uint32_t nstoff = (s^1)*S_SZ;
        const bool hasNext = (it + 1) < KCn;

        uint32_t g[16];
        if (hasNext) {
            const char* sh = (const char*)(Whi + ((size_t)(it+1)*COUT + co0)*40);
            for (int t2 = tid; t2 < 640; t2 += 256) cp16(sb + nstoff + t2*16, sh + t2*16);
            if (P3) {
                const char* sl = (const char*)(Wlo + ((size_t)(it+1)*COUT + co0)*40);
                for (int t2 = tid; t2 < 640; t2 += 256) cp16(sb + nstoff + S_AL + t2*16, sl + t2*16);
            }
            CP_COMMIT();
            int kg = (it+1)*32 + kb;
            int ci, ky, kx;
            if (KSZ == 3) { ci = kg/9; int r9 = kg - ci*9; ky = r9/3; kx = r9 - ky*3; }
            else          { ci = kg; ky = 0; kx = 0; }
            const uint32_t* src = Xin + ((size_t)(b*CIN + ci)*PR + (y + ky))*PC + kx + pxb;
#pragma unroll
            for (int i2 = 0; i2 < 16; i2++) g[i2] = src[8*i2];
        }

        // ---- mma on current stage ----
#pragma unroll
        for (int ks = 0; ks < 2; ks++) {
            const int k0 = ks*16;
            uint32_t Ah[4][4], Al[4][4], Bh[4][2], Bl[4][2];
            const int arow = warp_m*64 + (quad&1)*8 + qi;
            const int acol = k0 + (quad>>1)*8;
#pragma unroll
            for (int mf = 0; mf < 4; mf++) {
                uint32_t ad = stage + (uint32_t)((arow + mf*16)*40 + acol)*2;
                ldm_x4(Ah[mf], ad);
                if (P3) ldm_x4(Al[mf], ad + S_AL);
            }
            const int brow = k0 + (quad&1)*8 + qi;
#pragma unroll
            for (int p2 = 0; p2 < 2; p2++) {
                const int n0 = warp_n*32 + p2*16 + (quad>>1)*8;
                uint32_t bd = stage + S_BH + (uint32_t)(brow*136 + n0)*2;
                uint32_t r4[4];
                ldm_x4_t(r4, bd);
                Bh[p2*2][0]=r4[0]; Bh[p2*2][1]=r4[1]; Bh[p2*2+1][0]=r4[2]; Bh[p2*2+1][1]=r4[3];
                ldm_x4_t(r4, bd + 8704);
                Bl[p2*2][0]=r4[0]; Bl[p2*2][1]=r4[1]; Bl[p2*2+1][0]=r4[2]; Bl[p2*2+1][1]=r4[3];
            }
#pragma unroll
            for (int mf = 0; mf < 4; mf++)
#pragma unroll
                for (int nf = 0; nf < 4; nf++) {
                    mma16816f(acc[mf][nf], Ah[mf], Bh[nf]);
                    mma16816f(acc[mf][nf], Ah[mf], Bl[nf]);
                    if (P3) mma16816f(acc[mf][nf], Al[mf], Bh[nf]);
                }
        }

        if (hasNext) {
            int ro = kb*136 + pxb;
#pragma unroll
            for (int i2 = 0; i2 < 16; i2++) {
                *(unsigned short*)(smc + nstoff + S_BH + (ro + 8*i2)*2) = (unsigned short)(g[i2] & 0xffff);
                *(unsigned short*)(smc + nstoff + S_BL + (ro + 8*i2)*2) = (unsigned short)(g[i2] >> 16);
            }
        }
        CP_WAIT0();
        __syncthreads();
    }

    // ---- epilogue ----
    const int r = lane >> 2, cpx = (lane & 3)*2;
#pragma unroll
    for (int mf = 0; mf < 4; mf++) {
        int coA = co0 + warp_m*64 + mf*16 + r;
        float b0 = bias[coA], b1 = bias[coA + 8];
#pragma unroll
        for (int nf = 0; nf < 4; nf++) {
            int px = warp_n*32 + nf*8 + cpx;
            float v00 = acc[mf][nf][0] + b0, v01 = acc[mf][nf][1] + b0;
            float v10 = acc[mf][nf][2] + b1, v11 = acc[mf][nf][3] + b1;
            if (OPACK) {
                size_t r0 = ((size_t)(b*COUT + coA    )*PXR + (y+1))*PXC + (px+1);
                size_t r1 = ((size_t)(b*COUT + coA + 8)*PXR + (y+1))*PXC + (px+1);
                Ypk[r0]   = packhl(v00);
                Ypk[r0+1] = packhl(v01);
                Ypk[r1]   = packhl(v10);
                Ypk[r1+1] = packhl(v11);
            } else {
                float2 w0 = {v00, v01}, w1 = {v10, v11};
                *(float2*)&Yf[((size_t)(b*COUT + coA    ))*SP + y*WW + px] = w0;
                *(float2*)&Yf[((size_t)(b*COUT + coA + 8))*SP + y*WW + px] = w1;
            }
        }
    }
}

// ---------------------------------------------------------------------------
// Attention small kernels
__global__ __launch_bounds__(256)
void rownorm_kernel(const float* __restrict__ y2, float* __restrict__ nq, float* __restrict__ nk)
{
    const int r   = blockIdx.x;
    const int isK = (r >= 256);
    const int rr  = r & 255;
    const int b   = rr >> 7;
    const int ch  = rr & 127;
    const float* p = y2 + (size_t)b*C3*SP + (size_t)((isK ? DIM : 0) + ch)*SP;

    float s = 0.f;
    for (int i = threadIdx.x; i < SP; i += 256) {
        float v = p[i];
        s += v*v;
    }
    __shared__ float red[8];
#pragma unroll
    for (int o = 16; o; o >>= 1) s += __shfl_xor_sync(~0u, s, o);
    if ((threadIdx.x & 31) == 0) red[threadIdx.x >> 5] = s;
    __syncthreads();
    if (threadIdx.x == 0) {
        float t = 0.f;
        for (int w = 0; w < 8; w++) t += red[w];
        float n = fmaxf(sqrtf(t), 1e-12f);
        if (isK) nk[b*DIM + ch] = n;
        else     nq[b*DIM + ch] = n;
    }
}

__global__ void zeroS_kernel(float* __restrict__ Sm)
{
    Sm[blockIdx.x*blockDim.x + threadIdx.x] = 0.f;
}

__global__ __launch_bounds__(1024)
void scores_kernel(const float* __restrict__ y2, float* __restrict__ Sm)
{
    const int bh = blockIdx.x;
    const int b  = bh >> 2, h = bh & 3;
    const int s0 = blockIdx.y * 1024;
    const int c  = threadIdx.x >> 5;
    const int d  = threadIdx.x & 31;

    const float* q = y2 + (size_t)b*C3*SP + (size_t)(h*CH)*SP;
    const float* k = q + (size_t)DIM*SP;

    __shared__ float qs[32][33];
    __shared__ float ks[32][33];

    float acc = 0.f;
    for (int ss = 0; ss < 1024; ss += 32) {
        int row = threadIdx.x >> 5, col = threadIdx.x & 31;
        qs[row][col] = q[(size_t)row*SP + s0 + ss + col];
        ks[row][col] = k[(size_t)row*SP + s0 + ss + col];
        __syncthreads();
#pragma unroll
        for (int jj = 0; jj < 32; jj++)
            acc += qs[c][jj] * ks[d][jj];
        __syncthreads();
    }
    atomicAdd(&Sm[bh*1024 + c*32 + d], acc);
}

__global__ __launch_bounds__(1024)
void softmax_kernel(const float* __restrict__ Sm, const float* __restrict__ nq,
                    const float* __restrict__ nk, const float* __restrict__ temp,
                    float* __restrict__ Am)
{
    const int bh = blockIdx.x;
    const int b  = bh >> 2, h = bh & 3;
    const int c  = threadIdx.x >> 5;
    const int d  = threadIdx.x & 31;

    float qn = nq[b*DIM + h*CH + c];
    float kn = nk[b*DIM + h*CH + d];
    float v  = Sm[bh*1024 + c*32 + d] / (qn * kn) * temp[h];

    float m = v;
#pragma unroll
    for (int o = 16; o; o >>= 1) m = fmaxf(m, __shfl_xor_sync(~0u, m, o));
    float e = __expf(v - m);
    float s = e;
#pragma unroll
    for (int o = 16; o; o >>= 1) s += __shfl_xor_sync(~0u, s, o);
    Am[bh*1024 + c*32 + d] = e / s;
}

// out packed fp16 for po conv
__global__ __launch_bounds__(256)
void av_kernel(const float* __restrict__ y2, const float* __restrict__ Am,
               uint32_t* __restrict__ aopk)
{
    const int bh = blockIdx.x;
    const int b  = bh >> 2, h = bh & 3;
    const int s  = blockIdx.y * 256 + threadIdx.x;

    __shared__ float Asm[32][32];
    for (int l = threadIdx.x; l < 1024; l += 256)
        Asm[l >> 5][l & 31] = Am[bh*1024 + l];
    __syncthreads();

    const float* v = y2 + (size_t)b*C3*SP + (size_t)(2*DIM + h*CH)*SP;
    float vr[32];
#pragma unroll
    for (int d = 0; d < 32; d++) vr[d] = v[(size_t)d*SP + s];

    uint32_t* o = aopk + (size_t)b*DIM*SP + (size_t)(h*CH)*SP;
#pragma unroll
    for (int c = 0; c < 32; c++) {
        float acc = 0.f;
#pragma unroll
        for (int d = 0; d < 32; d++) acc += Asm[c][d]*vr[d];
        o[(size_t)c*SP + s] = packhl(acc);
    }
}

// ---------------------------------------------------------------------------
extern "C" void kernel_launch(void* const* d_in, const int* in_sizes, int n_in,
                              void* d_out, int out_size)
{
    const float* x      = (const float*)d_in[0];
    const float* qkv_r  = (const float*)d_in[1];
    const float* qkv_i  = (const float*)d_in[2];
    const float* qkv_j  = (const float*)d_in[3];
    const float* qkv_k  = (const float*)d_in[4];
    const float* qkv_b  = (const float*)d_in[5];
    const float* dw_r   = (const float*)d_in[6];
    const float* dw_i   = (const float*)d_in[7];
    const float* dw_j   = (const float*)d_in[8];
    const float* dw_k   = (const float*)d_in[9];
    const float* dw_b   = (const float*)d_in[10];
    const float* po_r   = (const float*)d_in[11];
    const float* po_i   = (const float*)d_in[12];
    const float* po_j   = (const float*)d_in[13];
    const float* po_k   = (const float*)d_in[14];
    const float* po_b   = (const float*)d_in[15];
    const float* temper = (const float*)d_in[16];
    float* out = (float*)d_out;

    __half *Wq_hi, *Wq_lo, *Wd_hi, *Wp_hi, *Wp_lo;
    uint32_t *Xq, *Xpk, *aopk;
    float *y2, *nq, *nk, *Sm, *Am;
    cudaGetSymbolAddress((void**)&Wq_hi, g_Wq_hi);
    cudaGetSymbolAddress((void**)&Wq_lo, g_Wq_lo);
    cudaGetSymbolAddress((void**)&Wd_hi, g_Wd_hi);
    cudaGetSymbolAddress((void**)&Wp_hi, g_Wp_hi);
    cudaGetSymbolAddress((void**)&Wp_lo, g_Wp_lo);
    cudaGetSymbolAddress((void**)&Xq,  g_Xq);
    cudaGetSymbolAddress((void**)&Xpk, g_Xpk);
    cudaGetSymbolAddress((void**)&aopk, g_aopk);
    cudaGetSymbolAddress((void**)&y2, g_y2);
    cudaGetSymbolAddress((void**)&nq, g_nq);
    cudaGetSymbolAddress((void**)&nk, g_nk);
    cudaGetSymbolAddress((void**)&Sm, g_S);
    cudaGetSymbolAddress((void**)&Am, g_A);

    const int SM3 = 75776;   // 3-pass stage*2
    const int SM2 = 55296;   // 2-pass stage*2
    cudaFuncSetAttribute(convmma_kernel<128,1,384,true,true>,
                         cudaFuncAttributeMaxDynamicSharedMemorySize, SM3);
    cudaFuncSetAttribute(convmma_kernel<384,3,384,false,false>,
                         cudaFuncAttributeMaxDynamicSharedMemorySize, SM2);
    cudaFuncSetAttribute(convmma_kernel<128,1,128,true,false>,
                         cudaFuncAttributeMaxDynamicSharedMemorySize, SM3);

    // 1) weight prep (Hamilton expand + fp16 split + chunk tiling)
    prepW_kernel<<<(16*96*32*1 + 255)/256, 256>>>(qkv_r, qkv_i, qkv_j, qkv_k, Wq_hi, Wq_lo, 96, 32, 1, 1);
    prepW_kernel<<<(16*96*96*9 + 255)/256, 256>>>(dw_r, dw_i, dw_j, dw_k, Wd_hi, Wd_hi, 96, 96, 9, 0);
    prepW_kernel<<<(16*32*32*1 + 255)/256, 256>>>(po_r, po_i, po_j, po_k, Wp_hi, Wp_lo, 32, 32, 1, 1);

    // 2) pack input; zero pad borders of qkv output buffer
    packX_kernel<<<(BATCH*DIM*SP + 255)/256, 256>>>(x, Xq);
    borderzero_kernel<<<(BATCH*C3*PXR*PXC + 255)/256, 256>>>(Xpk);

    // 3) qkv 1x1 conv (3-pass, writes padded packed fp16)
    convmma_kernel<128,1,384,true,true><<<dim3(BATCH*HH, 3), 256, SM3>>>(
        Wq_hi, Wq_lo, Xq, qkv_b, nullptr, Xpk, HH, WW);

    // 4) dw 3x3 conv (2-pass fp16, fp32 out)
    convmma_kernel<384,3,384,false,false><<<dim3(BATCH*HH, 3), 256, SM2>>>(
        Wd_hi, Wd_hi, Xpk, dw_b, y2, nullptr, PXR, PXC);

    // 5) attention
    rownorm_kernel<<<512, 256>>>(y2, nq, nk);
    zeroS_kernel<<<8, 1024>>>(Sm);
    scores_kernel<<<dim3(8, 16), 1024>>>(y2, Sm);
    softmax_kernel<<<8, 1024>>>(Sm, nq, nk, temper, Am);
    av_kernel<<<dim3(8, SP/256), 256>>>(y2, Am, aopk);

    // 6) po 1x1 conv (3-pass) -> out
    convmma_kernel<128,1,128,true,false><<<dim3(BATCH*HH, 1), 256, SM3>>>(
        Wp_hi, Wp_lo, aopk, po_b, out, nullptr, HH, WW);
}

// round 7
// speedup vs baseline: 6.3949x; 1.2613x over previous
#include <cuda_runtime.h>
#include <cuda_fp16.h>
#include <cstdint>
#include <math.h>

// Problem constants
#define BATCH 2
#define DIM   128
#define HH    128
#define WW    128
#define SP    (HH*WW)        // 16384
#define HEADS 4
#define CH    32
#define C3    384
#define PXR   130            // padded rows
#define PXC   132            // padded cols

// ---------------------------------------------------------------------------
// Scratch (__device__ globals: allocation-free rule)
__device__ __half  g_Wq_hi[4*C3*40];          // qkv weights chunked [chunk][co][40]
__device__ __half  g_Wq_lo[4*C3*40];
__device__ __half  g_Wd_hi[108*C3*40];        // dw weights (hi only, 1-pass)
__device__ __half  g_Wp_hi[4*DIM*40];         // po weights
__device__ __half  g_Wp_lo[4*DIM*40];
__device__ uint32_t       g_Xq [BATCH*DIM*SP];        // packed input x (fp16 hi|lo)
__device__ unsigned short g_Xpd[BATCH*C3*PXR*PXC];    // padded fp16 qkv output (hi only)
__device__ uint32_t       g_aopk[BATCH*DIM*SP];       // packed attention output
__device__ float g_y2[BATCH*C3*SP];           // dw conv output (q|k|v), fp32
__device__ float g_nq[BATCH*DIM];
__device__ float g_nk[BATCH*DIM];
__device__ float g_S[BATCH*HEADS*CH*CH];
__device__ float g_A[BATCH*HEADS*CH*CH];

// Hamilton block tables
__constant__ int   c_comp[4][4] = {{0,1,2,3},{1,0,3,2},{2,3,0,1},{3,2,1,0}};
__constant__ float c_sgn [4][4] = {{1.f,-1.f,-1.f,-1.f},
                                   {1.f, 1.f,-1.f, 1.f},
                                   {1.f, 1.f, 1.f,-1.f},
                                   {1.f,-1.f, 1.f, 1.f}};

// ---------------------------------------------------------------------------
__device__ __forceinline__ uint32_t smem_to_u32(const void* p) {
    uint32_t a;
    asm("{ .reg .u64 t; cvta.to.shared.u64 t, %1; cvt.u32.u64 %0, t; }" : "=r"(a) : "l"(p));
    return a;
}
__device__ __forceinline__ void cp16(uint32_t dst, const void* src) {
    asm volatile("cp.async.cg.shared.global [%0], [%1], 16;" :: "r"(dst), "l"(src) : "memory");
}
#define CP_COMMIT() asm volatile("cp.async.commit_group;" ::: "memory")
#define CP_WAIT0()  asm volatile("cp.async.wait_group 0;" ::: "memory")

__device__ __forceinline__ void ldm_x4(uint32_t* r, uint32_t addr) {
    asm volatile("ldmatrix.sync.aligned.m8n8.x4.shared.b16 {%0,%1,%2,%3}, [%4];"
        : "=r"(r[0]), "=r"(r[1]), "=r"(r[2]), "=r"(r[3]) : "r"(addr));
}
__device__ __forceinline__ void ldm_x4_t(uint32_t* r, uint32_t addr) {
    asm volatile("ldmatrix.sync.aligned.m8n8.x4.trans.shared.b16 {%0,%1,%2,%3}, [%4];"
        : "=r"(r[0]), "=r"(r[1]), "=r"(r[2]), "=r"(r[3]) : "r"(addr));
}
__device__ __forceinline__ void mma16816f(float* c, const uint32_t* a, const uint32_t* b) {
    asm volatile("mma.sync.aligned.m16n8k16.row.col.f32.f16.f16.f32 "
        "{%0,%1,%2,%3}, {%4,%5,%6,%7}, {%8,%9}, {%0,%1,%2,%3};"
        : "+f"(c[0]), "+f"(c[1]), "+f"(c[2]), "+f"(c[3])
        : "r"(a[0]), "r"(a[1]), "r"(a[2]), "r"(a[3]), "r"(b[0]), "r"(b[1]));
}

__device__ __forceinline__ uint32_t packhl(float v) {
    __half h = __float2half(v);
    __half l = __float2half(v - __half2float(h));
    return (uint32_t)__half_as_ushort(h) | ((uint32_t)__half_as_ushort(l) << 16);
}

// ---------------------------------------------------------------------------
// Hamilton expand + fp16 split + chunked tiling: dst[(chunk*COUT + co)*40 + kk]
__global__ void prepW_kernel(const float* __restrict__ r, const float* __restrict__ i,
                             const float* __restrict__ j, const float* __restrict__ k,
                             __half* __restrict__ Whi, __half* __restrict__ Wlo,
                             int Bo, int Bi, int K9, int writeLo)
{
    int total = 16*Bo*Bi*K9;
    int idx = blockIdx.x*blockDim.x + threadIdx.x;
    if (idx >= total) return;
    int KD = 4*Bi*K9;
    int co = idx / KD;
    int kidx = idx % KD;
    int ci = kidx / K9, r9 = kidx % K9;
    int br = co / Bo, o = co % Bo;
    int bc = ci / Bi, ic = ci % Bi;
    int comp = c_comp[br][bc];
    const float* src = (comp==0) ? r : (comp==1) ? i : (comp==2) ? j : k;
    float v = c_sgn[br][bc] * src[(o*Bi + ic)*K9 + r9];
    __half h = __float2half(v);
    int chunk = kidx >> 5, kk = kidx & 31;
    size_t dst = ((size_t)chunk*(4*Bo) + co)*40 + kk;
    Whi[dst] = h;
    if (writeLo) Wlo[dst] = __float2half(v - __half2float(h));
}

// Pack raw input x -> fp16 hi|lo u32
__global__ void packX_kernel(const float* __restrict__ x, uint32_t* __restrict__ Xq)
{
    int idx = blockIdx.x*blockDim.x + threadIdx.x;
    if (idx < BATCH*DIM*SP) Xq[idx] = packhl(x[idx]);
}

// Zero the border cells of the padded fp16 buffer
__global__ void borderzero_kernel(unsigned short* __restrict__ Xpd)
{
    int idx = blockIdx.x*blockDim.x + threadIdx.x;
    const int TOT = BATCH*C3*PXR*PXC;
    if (idx >= TOT) return;
    int col = idx % PXC;
    int row = (idx / PXC) % PXR;
    if (row == 0 || row == PXR-1 || col == 0 || col >= WW+1)
        Xpd[idx] = 0;
}

// ---------------------------------------------------------------------------
// Unified implicit-GEMM conv on mma.sync (fp16, fp32 accum)
// CTA: 128 co x 128 px (one image row), 8 warps (2x4), K in chunks of 32.
// PASSES: 3 = Ah*Bh + Ah*Bl + Al*Bh (packed u32 input); 1 = Ah*Bh (ushort input).
// OPACK: write padded fp16 hi (qkv); else fp32.
template<int CIN, int KSZ, int COUT, int PASSES, bool OPACK>
__global__ __launch_bounds__(256)
void convmma_kernel(const __half* __restrict__ Whi, const __half* __restrict__ Wlo,
                    const void* __restrict__ Xin, const float* __restrict__ bias,
                    float* __restrict__ Yf, unsigned short* __restrict__ Ypk,
                    int PR, int PC)
{
    constexpr bool P3  = (PASSES == 3);
    constexpr int K    = CIN*KSZ*KSZ;
    constexpr int KCn  = K/32;
    constexpr int S_AL = 10240;                    // A-lo offset (P3 only)
    constexpr int S_BH = P3 ? 20480 : 10240;
    constexpr int S_BL = S_BH + 8704;              // valid only if P3
    constexpr int S_SZ = S_BH + (P3 ? 2*8704 : 8704);

    extern __shared__ char smc[];
    const uint32_t sb = smem_to_u32(smc);
    const int tid = threadIdx.x, lane = tid & 31, wid = tid >> 5;
    const int bx = blockIdx.x;
    const int b  = bx >> 7;
    const int y  = bx & 127;
    const int co0 = blockIdx.y * 128;
    const int warp_m = wid >> 2;
    const int warp_n = wid & 3;

    float acc[4][4][4];
#pragma unroll
    for (int a = 0; a < 4; a++)
#pragma unroll
        for (int c = 0; c < 4; c++)
#pragma unroll
            for (int e = 0; e < 4; e++) acc[a][c][e] = 0.f;

    const int kb  = tid >> 3;   // k within chunk (0..31)
    const int pxb = tid & 7;    // px base

    // ---- prologue: stage chunk 0 ----
    {
        const char* sh = (const char*)(Whi + (size_t)co0*40);
        for (int t2 = tid; t2 < 640; t2 += 256) cp16(sb + t2*16, sh + t2*16);
        if (P3) {
            const char* sl = (const char*)(Wlo + (size_t)co0*40);
            for (int t2 = tid; t2 < 640; t2 += 256) cp16(sb + S_AL + t2*16, sl + t2*16);
        }
        CP_COMMIT();
        int kg = kb;
        int ci, ky, kx;
        if (KSZ == 3) { ci = kg/9; int r9 = kg - ci*9; ky = r9/3; kx = r9 - ky*3; }
        else          { ci = kg; ky = 0; kx = 0; }
        size_t base = ((size_t)(b*CIN + ci)*PR + (y + ky))*PC + kx + pxb;
        int ro = kb*136 + pxb;
        if (P3) {
            const uint32_t* src = (const uint32_t*)Xin + base;
            uint32_t g[16];
#pragma unroll
            for (int i2 = 0; i2 < 16; i2++) g[i2] = src[8*i2];
#pragma unroll
            for (int i2 = 0; i2 < 16; i2++) {
                *(unsigned short*)(smc + S_BH + (ro + 8*i2)*2) = (unsigned short)(g[i2] & 0xffff);
                *(unsigned short*)(smc + S_BL + (ro + 8*i2)*2) = (unsigned short)(g[i2] >> 16);
            }
        } else {
            const unsigned short* src = (const unsigned short*)Xin + base;
            unsigned short g[16];
#pragma unroll
            for (int i2 = 0; i2 < 16; i2++) g[i2] = src[8*i2];
#pragma unroll
            for (int i2 = 0; i2 < 16; i2++)
                *(unsigned short*)(smc + S_BH + (ro + 8*i2)*2) = g[i2];
        }
        CP_WAIT0();
        __syncthreads();
    }

    const int quad = lane >> 3, qi = lane & 7;

    for (int it = 0; it < KCn; it++) {
        const int s = it & 1;
        const uint32_t stage  = sb + s*S_SZ;
        const uint32_t nstoff = (s^1)*S_SZ;
        const bool hasNext = (it + 1) < KCn;

        uint32_t gp[16];
        unsigned short gs[16];
        if (hasNext) {
            const char* sh = (const char*)(Whi + ((size_t)(it+1)*COUT + co0)*40);
            for (int t2 = tid; t2 < 640; t2 += 256) cp16(sb + nstoff + t2*16, sh + t2*16);
            if (P3) {
                const char* sl = (const char*)(Wlo + ((size_t)(it+1)*COUT + co0)*40);
                for (int t2 = tid; t2 < 640; t2 += 256) cp16(sb + nstoff + S_AL + t2*16, sl + t2*16);
            }
            CP_COMMIT();
            int kg = (it+1)*32 + kb;
            int ci, ky, kx;
            if (KSZ == 3) { ci = kg/9; int r9 = kg - ci*9; ky = r9/3; kx = r9 - ky*3; }
            else          { ci = kg; ky = 0; kx = 0; }
            size_t base = ((size_t)(b*CIN + ci)*PR + (y + ky))*PC + kx + pxb;
            if (P3) {
                const uint32_t* src = (const uint32_t*)Xin + base;
#pragma unroll
                for (int i2 = 0; i2 < 16; i2++) gp[i2] = src[8*i2];
            } else {
                const unsigned short* src = (const unsigned short*)Xin + base;
#pragma unroll
                for (int i2 = 0; i2 < 16; i2++) gs[i2] = src[8*i2];
            }
        }

        // ---- mma on current stage ----
#pragma unroll
        for (int ks = 0; ks < 2; ks++) {
            const int k0 = ks*16;
            uint32_t Ah[4][4], Al[4][4], Bh[4][2], Bl[4][2];
            const int arow = warp_m*64 + (quad&1)*8 + qi;
            const int acol = k0 + (quad>>1)*8;
#pragma unroll
            for (int mf = 0; mf < 4; mf++) {
                uint32_t ad = stage + (uint32_t)((arow + mf*16)*40 + acol)*2;
                ldm_x4(Ah[mf], ad);
                if (P3) ldm_x4(Al[mf], ad + S_AL);
            }
            const int brow = k0 + (quad&1)*8 + qi;
#pragma unroll
            for (int p2 = 0; p2 < 2; p2++) {
                const int n0 = warp_n*32 + p2*16 + (quad>>1)*8;
                uint32_t bd = stage + S_BH + (uint32_t)(brow*136 + n0)*2;
                uint32_t r4[4];
                ldm_x4_t(r4, bd);
                Bh[p2*2][0]=r4[0]; Bh[p2*2][1]=r4[1]; Bh[p2*2+1][0]=r4[2]; Bh[p2*2+1][1]=r4[3];
                if (P3) {
                    ldm_x4_t(r4, bd + 8704);
                    Bl[p2*2][0]=r4[0]; Bl[p2*2][1]=r4[1]; Bl[p2*2+1][0]=r4[2]; Bl[p2*2+1][1]=r4[3];
                }
            }
#pragma unroll
            for (int mf = 0; mf < 4; mf++)
#pragma unroll
                for (int nf = 0; nf < 4; nf++) {
                    mma16816f(acc[mf][nf], Ah[mf], Bh[nf]);
                    if (P3) {
                        mma16816f(acc[mf][nf], Ah[mf], Bl[nf]);
                        mma16816f(acc[mf][nf], Al[mf], Bh[nf]);
                    }
                }
        }

        if (hasNext) {
            int ro = kb*136 + pxb;
            if (P3) {
#pragma unroll
                for (int i2 = 0; i2 < 16; i2++) {
                    *(unsigned short*)(smc + nstoff + S_BH + (ro + 8*i2)*2) = (unsigned short)(gp[i2] & 0xffff);
                    *(unsigned short*)(smc + nstoff + S_BL + (ro + 8*i2)*2) = (unsigned short)(gp[i2] >> 16);
                }
            } else {
#pragma unroll
                for (int i2 = 0; i2 < 16; i2++)
                    *(unsigned short*)(smc + nstoff + S_BH + (ro + 8*i2)*2) = gs[i2];
            }
        }
        CP_WAIT0();
        __syncthreads();
    }

    // ---- epilogue ----
    const int r = lane >> 2, cpx = (lane & 3)*2;
#pragma unroll
    for (int mf = 0; mf < 4; mf++) {
        int coA = co0 + warp_m*64 + mf*16 + r;
        float b0 = bias[coA], b1 = bias[coA + 8];
#pragma unroll
        for (int nf = 0; nf < 4; nf++) {
            int px = warp_n*32 + nf*8 + cpx;
            float v00 = acc[mf][nf][0] + b0, v01 = acc[mf][nf][1] + b0;
            float v10 = acc[mf][nf][2] + b1, v11 = acc[mf][nf][3] + b1;
            if (OPACK) {
                size_t r0 = ((size_t)(b*COUT + coA    )*PXR + (y+1))*PXC + (px+1);
                size_t r1 = ((size_t)(b*COUT + coA + 8)*PXR + (y+1))*PXC + (px+1);
                Ypk[r0]   = __half_as_ushort(__float2half(v00));
                Ypk[r0+1] = __half_as_ushort(__float2half(v01));
                Ypk[r1]   = __half_as_ushort(__float2half(v10));
                Ypk[r1+1] = __half_as_ushort(__float2half(v11));
            } else {
                float2 w0 = {v00, v01}, w1 = {v10, v11};
                *(float2*)&Yf[((size_t)(b*COUT + coA    ))*SP + y*WW + px] = w0;
                *(float2*)&Yf[((size_t)(b*COUT + coA + 8))*SP + y*WW + px] = w1;
            }
        }
    }
}

// ---------------------------------------------------------------------------
// Attention small kernels
__global__ __launch_bounds__(256)
void rownorm_kernel(const float* __restrict__ y2, float* __restrict__ nq, float* __restrict__ nk)
{
    const int r   = blockIdx.x;
    const int isK = (r >= 256);
    const int rr  = r & 255;
    const int b   = rr >> 7;
    const int ch  = rr & 127;
    const float* p = y2 + (size_t)b*C3*SP + (size_t)((isK ? DIM : 0) + ch)*SP;

    float s = 0.f;
    for (int i = threadIdx.x; i < SP; i += 256) {
        float v = p[i];
        s += v*v;
    }
    __shared__ float red[8];
#pragma unroll
    for (int o = 16; o; o >>= 1) s += __shfl_xor_sync(~0u, s, o);
    if ((threadIdx.x & 31) == 0) red[threadIdx.x >> 5] = s;
    __syncthreads();
    if (threadIdx.x == 0) {
        float t = 0.f;
        for (int w = 0; w < 8; w++) t += red[w];
        float n = fmaxf(sqrtf(t), 1e-12f);
        if (isK) nk[b*DIM + ch] = n;
        else     nq[b*DIM + ch] = n;
    }
}

__global__ void zeroS_kernel(float* __restrict__ Sm)
{
    Sm[blockIdx.x*blockDim.x + threadIdx.x] = 0.f;
}

__global__ __launch_bounds__(1024)
void scores_kernel(const float* __restrict__ y2, float* __restrict__ Sm)
{
    const int bh = blockIdx.x;
    const int b  = bh >> 2, h = bh & 3;
    const int s0 = blockIdx.y * 1024;
    const int c  = threadIdx.x >> 5;
    const int d  = threadIdx.x & 31;

    const float* q = y2 + (size_t)b*C3*SP + (size_t)(h*CH)*SP;
    const float* k = q + (size_t)DIM*SP;

    __shared__ float qs[32][33];
    __shared__ float ks[32][33];

    float acc = 0.f;
    for (int ss = 0; ss < 1024; ss += 32) {
        int row = threadIdx.x >> 5, col = threadIdx.x & 31;
        qs[row][col] = q[(size_t)row*SP + s0 + ss + col];
        ks[row][col] = k[(size_t)row*SP + s0 + ss + col];
        __syncthreads();
#pragma unroll
        for (int jj = 0; jj < 32; jj++)
            acc += qs[c][jj] * ks[d][jj];
        __syncthreads();
    }
    atomicAdd(&Sm[bh*1024 + c*32 + d], acc);
}

__global__ __launch_bounds__(1024)
void softmax_kernel(const float* __restrict__ Sm, const float* __restrict__ nq,
                    const float* __restrict__ nk, const float* __restrict__ temp,
                    float* __restrict__ Am)
{
    const int bh = blockIdx.x;
    const int b  = bh >> 2, h = bh & 3;
    const int c  = threadIdx.x >> 5;
    const int d  = threadIdx.x & 31;

    float qn = nq[b*DIM + h*CH + c];
    float kn = nk[b*DIM + h*CH + d];
    float v  = Sm[bh*1024 + c*32 + d] / (qn * kn) * temp[h];

    float m = v;
#pragma unroll
    for (int o = 16; o; o >>= 1) m = fmaxf(m, __shfl_xor_sync(~0u, m, o));
    float e = __expf(v - m);
    float s = e;
#pragma unroll
    for (int o = 16; o; o >>= 1) s += __shfl_xor_sync(~0u, s, o);
    Am[bh*1024 + c*32 + d] = e / s;
}

// out packed fp16 for po conv
__global__ __launch_bounds__(256)
void av_kernel(const float* __restrict__ y2, const float* __restrict__ Am,
               uint32_t* __restrict__ aopk)
{
    const int bh = blockIdx.x;
    const int b  = bh >> 2, h = bh & 3;
    const int s  = blockIdx.y * 256 + threadIdx.x;

    __shared__ float Asm[32][32];
    for (int l = threadIdx.x; l < 1024; l += 256)
        Asm[l >> 5][l & 31] = Am[bh*1024 + l];
    __syncthreads();

    const float* v = y2 + (size_t)b*C3*SP + (size_t)(2*DIM + h*CH)*SP;
    float vr[32];
#pragma unroll
    for (int d = 0; d < 32; d++) vr[d] = v[(size_t)d*SP + s];

    uint32_t* o = aopk + (size_t)b*DIM*SP + (size_t)(h*CH)*SP;
#pragma unroll
    for (int c = 0; c < 32; c++) {
        float acc = 0.f;
#pragma unroll
        for (int d = 0; d < 32; d++) acc += Asm[c][d]*vr[d];
        o[(size_t)c*SP + s] = packhl(acc);
    }
}

// ---------------------------------------------------------------------------
extern "C" void kernel_launch(void* const* d_in, const int* in_sizes, int n_in,
                              void* d_out, int out_size)
{
    const float* x      = (const float*)d_in[0];
    const float* qkv_r  = (const float*)d_in[1];
    const float* qkv_i  = (const float*)d_in[2];
    const float* qkv_j  = (const float*)d_in[3];
    const float* qkv_k  = (const float*)d_in[4];
    const float* qkv_b  = (const float*)d_in[5];
    const float* dw_r   = (const float*)d_in[6];
    const float* dw_i   = (const float*)d_in[7];
    const float* dw_j   = (const float*)d_in[8];
    const float* dw_k   = (const float*)d_in[9];
    const float* dw_b   = (const float*)d_in[10];
    const float* po_r   = (const float*)d_in[11];
    const float* po_i   = (const float*)d_in[12];
    const float* po_j   = (const float*)d_in[13];
    const float* po_k   = (const float*)d_in[14];
    const float* po_b   = (const float*)d_in[15];
    const float* temper = (const float*)d_in[16];
    float* out = (float*)d_out;

    __half *Wq_hi, *Wq_lo, *Wd_hi, *Wp_hi, *Wp_lo;
    uint32_t *Xq, *aopk;
    unsigned short *Xpd;
    float *y2, *nq, *nk, *Sm, *Am;
    cudaGetSymbolAddress((void**)&Wq_hi, g_Wq_hi);
    cudaGetSymbolAddress((void**)&Wq_lo, g_Wq_lo);
    cudaGetSymbolAddress((void**)&Wd_hi, g_Wd_hi);
    cudaGetSymbolAddress((void**)&Wp_hi, g_Wp_hi);
    cudaGetSymbolAddress((void**)&Wp_lo, g_Wp_lo);
    cudaGetSymbolAddress((void**)&Xq,  g_Xq);
    cudaGetSymbolAddress((void**)&Xpd, g_Xpd);
    cudaGetSymbolAddress((void**)&aopk, g_aopk);
    cudaGetSymbolAddress((void**)&y2, g_y2);
    cudaGetSymbolAddress((void**)&nq, g_nq);
    cudaGetSymbolAddress((void**)&nk, g_nk);
    cudaGetSymbolAddress((void**)&Sm, g_S);
    cudaGetSymbolAddress((void**)&Am, g_A);

    const int SM3 = 75776;   // 3-pass stage*2
    const int SM1 = 37888;   // 1-pass stage*2
    cudaFuncSetAttribute(convmma_kernel<128,1,384,3,true>,
                         cudaFuncAttributeMaxDynamicSharedMemorySize, SM3);
    cudaFuncSetAttribute(convmma_kernel<384,3,384,1,false>,
                         cudaFuncAttributeMaxDynamicSharedMemorySize, SM1);
    cudaFuncSetAttribute(convmma_kernel<128,1,128,3,false>,
                         cudaFuncAttributeMaxDynamicSharedMemorySize, SM3);

    // 1) weight prep (Hamilton expand + fp16 split + chunk tiling)
    prepW_kernel<<<(16*96*32*1 + 255)/256, 256>>>(qkv_r, qkv_i, qkv_j, qkv_k, Wq_hi, Wq_lo, 96, 32, 1, 1);
    prepW_kernel<<<(16*96*96*9 + 255)/256, 256>>>(dw_r, dw_i, dw_j, dw_k, Wd_hi, Wd_hi, 96, 96, 9, 0);
    prepW_kernel<<<(16*32*32*1 + 255)/256, 256>>>(po_r, po_i, po_j, po_k, Wp_hi, Wp_lo, 32, 32, 1, 1);

    // 2) pack input; zero pad borders of qkv output buffer
    packX_kernel<<<(BATCH*DIM*SP + 255)/256, 256>>>(x, Xq);
    borderzero_kernel<<<(BATCH*C3*PXR*PXC + 255)/256, 256>>>(Xpd);

    // 3) qkv 1x1 conv (3-pass, writes padded fp16 hi)
    convmma_kernel<128,1,384,3,true><<<dim3(BATCH*HH, 3), 256, SM3>>>(
        Wq_hi, Wq_lo, Xq, qkv_b, nullptr, Xpd, HH, WW);

    // 4) dw 3x3 conv (1-pass fp16, fp32 out)
    convmma_kernel<384,3,384,1,false><<<dim3(BATCH*HH, 3), 256, SM1>>>(
        Wd_hi, Wd_hi, Xpd, dw_b, y2, nullptr, PXR, PXC);

    // 5) attention
    rownorm_kernel<<<512, 256>>>(y2, nq, nk);
    zeroS_kernel<<<8, 1024>>>(Sm);
    scores_kernel<<<dim3(8, 16), 1024>>>(y2, Sm);
    softmax_kernel<<<8, 1024>>>(Sm, nq, nk, temper, Am);
    av_kernel<<<dim3(8, SP/256), 256>>>(y2, Am, aopk);

    // 6) po 1x1 conv (3-pass) -> out
    convmma_kernel<128,1,128,3,false><<<dim3(BATCH*HH, 1), 256, SM3>>>(
        Wp_hi, Wp_lo, aopk, po_b, out, nullptr, HH, WW);
}

// round 8
// speedup vs baseline: 7.0405x; 1.1010x over previous
#include <cuda_runtime.h>
#include <cuda_fp16.h>
#include <cstdint>
#include <math.h>

// Problem constants
#define BATCH 2
#define DIM   128
#define HH    128
#define WW    128
#define SP    (HH*WW)        // 16384
#define HEADS 4
#define CH    32
#define C3    384
#define PXR   130            // padded rows
#define PXC   132            // padded cols

// ---------------------------------------------------------------------------
// Scratch (__device__ globals: allocation-free rule)
__device__ __half  g_Wq_hi[4*C3*40];          // qkv weights chunked [chunk][co][40]
__device__ __half  g_Wq_lo[4*C3*40];
__device__ __half  g_Wd_hi[108*C3*40];        // dw weights (hi only, 1-pass)
__device__ __half  g_Wp_hi[4*DIM*40];         // po weights
__device__ __half  g_Wp_lo[4*DIM*40];
__device__ unsigned short g_Xpd[BATCH*C3*PXR*PXC];    // padded fp16 qkv output (hi only)
__device__ unsigned short g_y2h[BATCH*C3*SP];         // dw conv output (q|k|v), fp16
__device__ uint32_t       g_aopk[BATCH*DIM*SP];       // packed attention output (hi|lo)
__device__ float g_nq2[BATCH*DIM];            // sum of squares (q rows)
__device__ float g_nk2[BATCH*DIM];
__device__ float g_S[BATCH*HEADS*CH*CH];
__device__ float g_A[BATCH*HEADS*CH*CH];

// Hamilton block tables
__constant__ int   c_comp[4][4] = {{0,1,2,3},{1,0,3,2},{2,3,0,1},{3,2,1,0}};
__constant__ float c_sgn [4][4] = {{1.f,-1.f,-1.f,-1.f},
                                   {1.f, 1.f,-1.f, 1.f},
                                   {1.f, 1.f, 1.f,-1.f},
                                   {1.f,-1.f, 1.f, 1.f}};

// ---------------------------------------------------------------------------
__device__ __forceinline__ uint32_t smem_to_u32(const void* p) {
    uint32_t a;
    asm("{ .reg .u64 t; cvta.to.shared.u64 t, %1; cvt.u32.u64 %0, t; }" : "=r"(a) : "l"(p));
    return a;
}
__device__ __forceinline__ void cp16(uint32_t dst, const void* src) {
    asm volatile("cp.async.cg.shared.global [%0], [%1], 16;" :: "r"(dst), "l"(src) : "memory");
}
#define CP_COMMIT() asm volatile("cp.async.commit_group;" ::: "memory")
#define CP_WAIT0()  asm volatile("cp.async.wait_group 0;" ::: "memory")

__device__ __forceinline__ void ldm_x4(uint32_t* r, uint32_t addr) {
    asm volatile("ldmatrix.sync.aligned.m8n8.x4.shared.b16 {%0,%1,%2,%3}, [%4];"
        : "=r"(r[0]), "=r"(r[1]), "=r"(r[2]), "=r"(r[3]) : "r"(addr));
}
__device__ __forceinline__ void ldm_x4_t(uint32_t* r, uint32_t addr) {
    asm volatile("ldmatrix.sync.aligned.m8n8.x4.trans.shared.b16 {%0,%1,%2,%3}, [%4];"
        : "=r"(r[0]), "=r"(r[1]), "=r"(r[2]), "=r"(r[3]) : "r"(addr));
}
__device__ __forceinline__ void mma16816f(float* c, const uint32_t* a, const uint32_t* b) {
    asm volatile("mma.sync.aligned.m16n8k16.row.col.f32.f16.f16.f32 "
        "{%0,%1,%2,%3}, {%4,%5,%6,%7}, {%8,%9}, {%0,%1,%2,%3};"
        : "+f"(c[0]), "+f"(c[1]), "+f"(c[2]), "+f"(c[3])
        : "r"(a[0]), "r"(a[1]), "r"(a[2]), "r"(a[3]), "r"(b[0]), "r"(b[1]));
}

__device__ __forceinline__ uint32_t packhl(float v) {
    __half h = __float2half(v);
    __half l = __float2half(v - __half2float(h));
    return (uint32_t)__half_as_ushort(h) | ((uint32_t)__half_as_ushort(l) << 16);
}

// ---------------------------------------------------------------------------
// Hamilton expand + fp16 split + chunked tiling: dst[(chunk*COUT + co)*40 + kk]
__global__ void prepW_kernel(const float* __restrict__ r, const float* __restrict__ i,
                             const float* __restrict__ j, const float* __restrict__ k,
                             __half* __restrict__ Whi, __half* __restrict__ Wlo,
                             int Bo, int Bi, int K9, int writeLo)
{
    int total = 16*Bo*Bi*K9;
    int idx = blockIdx.x*blockDim.x + threadIdx.x;
    if (idx >= total) return;
    int KD = 4*Bi*K9;
    int co = idx / KD;
    int kidx = idx % KD;
    int ci = kidx / K9, r9 = kidx % K9;
    int br = co / Bo, o = co % Bo;
    int bc = ci / Bi, ic = ci % Bi;
    int comp = c_comp[br][bc];
    const float* src = (comp==0) ? r : (comp==1) ? i : (comp==2) ? j : k;
    float v = c_sgn[br][bc] * src[(o*Bi + ic)*K9 + r9];
    __half h = __float2half(v);
    int chunk = kidx >> 5, kk = kidx & 31;
    size_t dst = ((size_t)chunk*(4*Bo) + co)*40 + kk;
    Whi[dst] = h;
    if (writeLo) Wlo[dst] = __float2half(v - __half2float(h));
}

// Zero ONLY border cells of the padded fp16 buffer (776 per plane)
#define BPER (2*PXC + 128*4)
__global__ void borderzero_kernel(unsigned short* __restrict__ Xpd)
{
    int idx = blockIdx.x*blockDim.x + threadIdx.x;
    if (idx >= BATCH*C3*BPER) return;
    int plane = idx / BPER, r = idx % BPER;
    unsigned short* p = Xpd + (size_t)plane*PXR*PXC;
    int row, col;
    if (r < 2*PXC) { row = (r < PXC) ? 0 : (PXR-1); col = r % PXC; }
    else { int t = r - 2*PXC; row = 1 + (t >> 2); int c4 = t & 3; col = (c4==0) ? 0 : (128 + c4); }
    p[row*PXC + col] = 0;
}

// Zero scores + norm accumulators
__global__ void zeroSN_kernel(float* __restrict__ Sm, float* __restrict__ nq2, float* __restrict__ nk2)
{
    int i = blockIdx.x*blockDim.x + threadIdx.x;
    if (i < 8192) Sm[i] = 0.f;
    if (i < 256) nq2[i] = 0.f;
    else if (i < 512) nk2[i-256] = 0.f;
}

// ---------------------------------------------------------------------------
// Unified implicit-GEMM conv on mma.sync (fp16, fp32 accum)
// CTA: 128 co x 128 px (one image row), 8 warps (2x4), K chunks of 32.
// PASSES: 1 = Ah*Bh                (ushort input)
//         2 = Ah*Bh + Al*Bh        (float input, hi(x) as B)
//         3 = Ah*Bh + Ah*Bl + Al*Bh (packed u32 input)
// OUTMODE: 0 = float flat, 1 = ushort padded (PXR/PXC), 2 = ushort flat
template<int CIN, int KSZ, int COUT, int PASSES, int OUTMODE>
__global__ __launch_bounds__(256)
void convmma_kernel(const __half* __restrict__ Whi, const __half* __restrict__ Wlo,
                    const void* __restrict__ Xin, const float* __restrict__ bias,
                    float* __restrict__ Yf, unsigned short* __restrict__ Yh,
                    int PR, int PC)
{
    constexpr bool HAS_AL = (PASSES >= 2);
    constexpr bool HAS_BL = (PASSES == 3);
    constexpr int K    = CIN*KSZ*KSZ;
    constexpr int KCn  = K/32;
    constexpr int S_AL = 10240;
    constexpr int S_BH = HAS_AL ? 20480 : 10240;
    constexpr int S_BL = S_BH + 8704;
    constexpr int S_SZ = S_BH + (HAS_BL ? 2*8704 : 8704);

    extern __shared__ char smc[];
    const uint32_t sb = smem_to_u32(smc);
    const int tid = threadIdx.x, lane = tid & 31, wid = tid >> 5;
    const int bx = blockIdx.x;
    const int b  = bx >> 7;
    const int y  = bx & 127;
    const int co0 = blockIdx.y * 128;
    const int warp_m = wid >> 2;
    const int warp_n = wid & 3;

    float acc[4][4][4];
#pragma unroll
    for (int a = 0; a < 4; a++)
#pragma unroll
        for (int c = 0; c < 4; c++)
#pragma unroll
            for (int e = 0; e < 4; e++) acc[a][c][e] = 0.f;

    const int kb  = tid >> 3;   // k within chunk (0..31)
    const int pxb = tid & 7;    // px base

    // ---- prologue: stage chunk 0 ----
    {
        const char* sh = (const char*)(Whi + (size_t)co0*40);
        for (int t2 = tid; t2 < 640; t2 += 256) cp16(sb + t2*16, sh + t2*16);
        if (HAS_AL) {
            const char* sl = (const char*)(Wlo + (size_t)co0*40);
            for (int t2 = tid; t2 < 640; t2 += 256) cp16(sb + S_AL + t2*16, sl + t2*16);
        }
        CP_COMMIT();
        int kg = kb;
        int ci, ky, kx;
        if (KSZ == 3) { ci = kg/9; int r9 = kg - ci*9; ky = r9/3; kx = r9 - ky*3; }
        else          { ci = kg; ky = 0; kx = 0; }
        size_t base = ((size_t)(b*CIN + ci)*PR + (y + ky))*PC + kx + pxb;
        int ro = kb*136 + pxb;
        if constexpr (PASSES == 3) {
            const uint32_t* src = (const uint32_t*)Xin + base;
            uint32_t g[16];
#pragma unroll
            for (int i2 = 0; i2 < 16; i2++) g[i2] = src[8*i2];
#pragma unroll
            for (int i2 = 0; i2 < 16; i2++) {
                *(unsigned short*)(smc + S_BH + (ro + 8*i2)*2) = (unsigned short)(g[i2] & 0xffff);
                *(unsigned short*)(smc + S_BL + (ro + 8*i2)*2) = (unsigned short)(g[i2] >> 16);
            }
        } else if constexpr (PASSES == 2) {
            const float* src = (const float*)Xin + base;
            float g[16];
#pragma unroll
            for (int i2 = 0; i2 < 16; i2++) g[i2] = src[8*i2];
#pragma unroll
            for (int i2 = 0; i2 < 16; i2++)
                *(unsigned short*)(smc + S_BH + (ro + 8*i2)*2) = __half_as_ushort(__float2half(g[i2]));
        } else {
            const unsigned short* src = (const unsigned short*)Xin + base;
            unsigned short g[16];
#pragma unroll
            for (int i2 = 0; i2 < 16; i2++) g[i2] = src[8*i2];
#pragma unroll
            for (int i2 = 0; i2 < 16; i2++)
                *(unsigned short*)(smc + S_BH + (ro + 8*i2)*2) = g[i2];
        }
        CP_WAIT0();
        __syncthreads();
    }

    const int quad = lane >> 3, qi = lane & 7;

    for (int it = 0; it < KCn; it++) {
        const int s = it & 1;
        const uint32_t stage  = sb + s*S_SZ;
        const uint32_t nstoff = (s^1)*S_SZ;
        const bool hasNext = (it + 1) < KCn;

        uint32_t gp[16];
        float gf[16];
        unsigned short gs[16];
        if (hasNext) {
            const char* sh = (const char*)(Whi + ((size_t)(it+1)*COUT + co0)*40);
            for (int t2 = tid; t2 < 640; t2 += 256) cp16(sb + nstoff + t2*16, sh + t2*16);
            if (HAS_AL) {
                const char* sl = (const char*)(Wlo + ((size_t)(it+1)*COUT + co0)*40);
                for (int t2 = tid; t2 < 640; t2 += 256) cp16(sb + nstoff + S_AL + t2*16, sl + t2*16);
            }
            CP_COMMIT();
            int kg = (it+1)*32 + kb;
            int ci, ky, kx;
            if (KSZ == 3) { ci = kg/9; int r9 = kg - ci*9; ky = r9/3; kx = r9 - ky*3; }
            else          { ci = kg; ky = 0; kx = 0; }
            size_t base = ((size_t)(b*CIN + ci)*PR + (y + ky))*PC + kx + pxb;
            if constexpr (PASSES == 3) {
                const uint32_t* src = (const uint32_t*)Xin + base;
#pragma unroll
                for (int i2 = 0; i2 < 16; i2++) gp[i2] = src[8*i2];
            } else if constexpr (PASSES == 2) {
                const float* src = (const float*)Xin + base;
#pragma unroll
                for (int i2 = 0; i2 < 16; i2++) gf[i2] = src[8*i2];
            } else {
                const unsigned short* src = (const unsigned short*)Xin + base;
#pragma unroll
                for (int i2 = 0; i2 < 16; i2++) gs[i2] = src[8*i2];
            }
        }

        // ---- mma on current stage ----
#pragma unroll
        for (int ks = 0; ks < 2; ks++) {
            const int k0 = ks*16;
            uint32_t Ah[4][4], Al[4][4], Bh[4][2], Bl[4][2];
            const int arow = warp_m*64 + (quad&1)*8 + qi;
            const int acol = k0 + (quad>>1)*8;
#pragma unroll
            for (int mf = 0; mf < 4; mf++) {
                uint32_t ad = stage + (uint32_t)((arow + mf*16)*40 + acol)*2;
                ldm_x4(Ah[mf], ad);
                if (HAS_AL) ldm_x4(Al[mf], ad + S_AL);
            }
            const int brow = k0 + (quad&1)*8 + qi;
#pragma unroll
            for (int p2 = 0; p2 < 2; p2++) {
                const int n0 = warp_n*32 + p2*16 + (quad>>1)*8;
                uint32_t bd = stage + S_BH + (uint32_t)(brow*136 + n0)*2;
                uint32_t r4[4];
                ldm_x4_t(r4, bd);
                Bh[p2*2][0]=r4[0]; Bh[p2*2][1]=r4[1]; Bh[p2*2+1][0]=r4[2]; Bh[p2*2+1][1]=r4[3];
                if (HAS_BL) {
                    ldm_x4_t(r4, bd + 8704);
                    Bl[p2*2][0]=r4[0]; Bl[p2*2][1]=r4[1]; Bl[p2*2+1][0]=r4[2]; Bl[p2*2+1][1]=r4[3];
                }
            }
#pragma unroll
            for (int mf = 0; mf < 4; mf++)
#pragma unroll
                for (int nf = 0; nf < 4; nf++) {
                    mma16816f(acc[mf][nf], Ah[mf], Bh[nf]);
                    if (HAS_BL) mma16816f(acc[mf][nf], Ah[mf], Bl[nf]);
                    if (HAS_AL) mma16816f(acc[mf][nf], Al[mf], Bh[nf]);
                }
        }

        if (hasNext) {
            int ro = kb*136 + pxb;
            if constexpr (PASSES == 3) {
#pragma unroll
                for (int i2 = 0; i2 < 16; i2++) {
                    *(unsigned short*)(smc + nstoff + S_BH + (ro + 8*i2)*2) = (unsigned short)(gp[i2] & 0xffff);
                    *(unsigned short*)(smc + nstoff + S_BL + (ro + 8*i2)*2) = (unsigned short)(gp[i2] >> 16);
                }
            } else if constexpr (PASSES == 2) {
#pragma unroll
                for (int i2 = 0; i2 < 16; i2++)
                    *(unsigned short*)(smc + nstoff + S_BH + (ro + 8*i2)*2) = __half_as_ushort(__float2half(gf[i2]));
            } else {
#pragma unroll
                for (int i2 = 0; i2 < 16; i2++)
                    *(unsigned short*)(smc + nstoff + S_BH + (ro + 8*i2)*2) = gs[i2];
            }
        }
        CP_WAIT0();
        __syncthreads();
    }

    // ---- epilogue ----
    const int r = lane >> 2, cpx = (lane & 3)*2;
#pragma unroll
    for (int mf = 0; mf < 4; mf++) {
        int coA = co0 + warp_m*64 + mf*16 + r;
        float b0 = bias[coA], b1 = bias[coA + 8];
#pragma unroll
        for (int nf = 0; nf < 4; nf++) {
            int px = warp_n*32 + nf*8 + cpx;
            float v00 = acc[mf][nf][0] + b0, v01 = acc[mf][nf][1] + b0;
            float v10 = acc[mf][nf][2] + b1, v11 = acc[mf][nf][3] + b1;
            if constexpr (OUTMODE == 1) {
                size_t r0 = ((size_t)(b*COUT + coA    )*PXR + (y+1))*PXC + (px+1);
                size_t r1 = ((size_t)(b*COUT + coA + 8)*PXR + (y+1))*PXC + (px+1);
                Yh[r0]   = __half_as_ushort(__float2half(v00));
                Yh[r0+1] = __half_as_ushort(__float2half(v01));
                Yh[r1]   = __half_as_ushort(__float2half(v10));
                Yh[r1+1] = __half_as_ushort(__float2half(v11));
            } else if constexpr (OUTMODE == 2) {
                uint32_t p0 = (uint32_t)__half_as_ushort(__float2half(v00)) |
                              ((uint32_t)__half_as_ushort(__float2half(v01)) << 16);
                uint32_t p1 = (uint32_t)__half_as_ushort(__float2half(v10)) |
                              ((uint32_t)__half_as_ushort(__float2half(v11)) << 16);
                *(uint32_t*)&Yh[((size_t)(b*COUT + coA    ))*SP + y*WW + px] = p0;
                *(uint32_t*)&Yh[((size_t)(b*COUT + coA + 8))*SP + y*WW + px] = p1;
            } else {
                float2 w0 = {v00, v01}, w1 = {v10, v11};
                *(float2*)&Yf[((size_t)(b*COUT + coA    ))*SP + y*WW + px] = w0;
                *(float2*)&Yf[((size_t)(b*COUT + coA + 8))*SP + y*WW + px] = w1;
            }
        }
    }
}

// ---------------------------------------------------------------------------
// scores + fused norm accumulation. grid (8,16), block 1024
__global__ __launch_bounds__(1024)
void scores_kernel(const unsigned short* __restrict__ y2h, float* __restrict__ Sm,
                   float* __restrict__ nq2, float* __restrict__ nk2)
{
    const int bh = blockIdx.x;
    const int b  = bh >> 2, h = bh & 3;
    const int s0 = blockIdx.y * 1024;
    const int c  = threadIdx.x >> 5;
    const int d  = threadIdx.x & 31;

    const unsigned short* q = y2h + (size_t)b*C3*SP + (size_t)(h*CH)*SP;
    const unsigned short* k = q + (size_t)DIM*SP;

    __shared__ float qs[32][33];
    __shared__ float ks[32][33];

    float acc = 0.f, sq = 0.f, sk = 0.f;
    for (int ss = 0; ss < 1024; ss += 32) {
        int row = threadIdx.x >> 5, col = threadIdx.x & 31;
        qs[row][col] = __half2float(__ushort_as_half(q[(size_t)row*SP + s0 + ss + col]));
        ks[row][col] = __half2float(__ushort_as_half(k[(size_t)row*SP + s0 + ss + col]));
        __syncthreads();
#pragma unroll
        for (int jj = 0; jj < 32; jj++) {
            float qa = qs[c][jj], kb = ks[d][jj];
            acc += qa*kb;
            sq  += qa*qa;
            sk  += kb*kb;
        }
        __syncthreads();
    }
    atomicAdd(&Sm[bh*1024 + c*32 + d], acc);
    if (d == 0) atomicAdd(&nq2[b*DIM + h*CH + c], sq);
    if (c == 0) atomicAdd(&nk2[b*DIM + h*CH + d], sk);
}

__global__ __launch_bounds__(1024)
void softmax_kernel(const float* __restrict__ Sm, const float* __restrict__ nq2,
                    const float* __restrict__ nk2, const float* __restrict__ temp,
                    float* __restrict__ Am)
{
    const int bh = blockIdx.x;
    const int b  = bh >> 2, h = bh & 3;
    const int c  = threadIdx.x >> 5;
    const int d  = threadIdx.x & 31;

    float qn = fmaxf(sqrtf(nq2[b*DIM + h*CH + c]), 1e-12f);
    float kn = fmaxf(sqrtf(nk2[b*DIM + h*CH + d]), 1e-12f);
    float v  = Sm[bh*1024 + c*32 + d] / (qn * kn) * temp[h];

    float m = v;
#pragma unroll
    for (int o = 16; o; o >>= 1) m = fmaxf(m, __shfl_xor_sync(~0u, m, o));
    float e = __expf(v - m);
    float s = e;
#pragma unroll
    for (int o = 16; o; o >>= 1) s += __shfl_xor_sync(~0u, s, o);
    Am[bh*1024 + c*32 + d] = e / s;
}

// out packed fp16 (hi|lo) for po conv
__global__ __launch_bounds__(256)
void av_kernel(const unsigned short* __restrict__ y2h, const float* __restrict__ Am,
               uint32_t* __restrict__ aopk)
{
    const int bh = blockIdx.x;
    const int b  = bh >> 2, h = bh & 3;
    const int s  = blockIdx.y * 256 + threadIdx.x;

    __shared__ float Asm[32][32];
    for (int l = threadIdx.x; l < 1024; l += 256)
        Asm[l >> 5][l & 31] = Am[bh*1024 + l];
    __syncthreads();

    const unsigned short* v = y2h + (size_t)b*C3*SP + (size_t)(2*DIM + h*CH)*SP;
    float vr[32];
#pragma unroll
    for (int d = 0; d < 32; d++) vr[d] = __half2float(__ushort_as_half(v[(size_t)d*SP + s]));

    uint32_t* o = aopk + (size_t)b*DIM*SP + (size_t)(h*CH)*SP;
#pragma unroll
    for (int c = 0; c < 32; c++) {
        float acc = 0.f;
#pragma unroll
        for (int d = 0; d < 32; d++) acc += Asm[c][d]*vr[d];
        o[(size_t)c*SP + s] = packhl(acc);
    }
}

// ---------------------------------------------------------------------------
extern "C" void kernel_launch(void* const* d_in, const int* in_sizes, int n_in,
                              void* d_out, int out_size)
{
    const float* x      = (const float*)d_in[0];
    const float* qkv_r  = (const float*)d_in[1];
    const float* qkv_i  = (const float*)d_in[2];
    const float* qkv_j  = (const float*)d_in[3];
    const float* qkv_k  = (const float*)d_in[4];
    const float* qkv_b  = (const float*)d_in[5];
    const float* dw_r   = (const float*)d_in[6];
    const float* dw_i   = (const float*)d_in[7];
    const float* dw_j   = (const float*)d_in[8];
    const float* dw_k   = (const float*)d_in[9];
    const float* dw_b   = (const float*)d_in[10];
    const float* po_r   = (const float*)d_in[11];
    const float* po_i   = (const float*)d_in[12];
    const float* po_j   = (const float*)d_in[13];
    const float* po_k   = (const float*)d_in[14];
    const float* po_b   = (const float*)d_in[15];
    const float* temper = (const float*)d_in[16];
    float* out = (float*)d_out;

    __half *Wq_hi, *Wq_lo, *Wd_hi, *Wp_hi, *Wp_lo;
    uint32_t *aopk;
    unsigned short *Xpd, *y2h;
    float *nq2, *nk2, *Sm, *Am;
    cudaGetSymbolAddress((void**)&Wq_hi, g_Wq_hi);
    cudaGetSymbolAddress((void**)&Wq_lo, g_Wq_lo);
    cudaGetSymbolAddress((void**)&Wd_hi, g_Wd_hi);
    cudaGetSymbolAddress((void**)&Wp_hi, g_Wp_hi);
    cudaGetSymbolAddress((void**)&Wp_lo, g_Wp_lo);
    cudaGetSymbolAddress((void**)&Xpd, g_Xpd);
    cudaGetSymbolAddress((void**)&y2h, g_y2h);
    cudaGetSymbolAddress((void**)&aopk, g_aopk);
    cudaGetSymbolAddress((void**)&nq2, g_nq2);
    cudaGetSymbolAddress((void**)&nk2, g_nk2);
    cudaGetSymbolAddress((void**)&Sm, g_S);
    cudaGetSymbolAddress((void**)&Am, g_A);

    const int SMQ = 58368;   // 2-pass stage*2 (A hi+lo, B hi)
    const int SM1 = 37888;   // 1-pass stage*2
    const int SM3 = 75776;   // 3-pass stage*2
    cudaFuncSetAttribute(convmma_kernel<128,1,384,2,1>,
                         cudaFuncAttributeMaxDynamicSharedMemorySize, SMQ);
    cudaFuncSetAttribute(convmma_kernel<384,3,384,1,2>,
                         cudaFuncAttributeMaxDynamicSharedMemorySize, SM1);
    cudaFuncSetAttribute(convmma_kernel<128,1,128,3,0>,
                         cudaFuncAttributeMaxDynamicSharedMemorySize, SM3);

    // 1) weight prep (Hamilton expand + fp16 split + chunk tiling)
    prepW_kernel<<<(16*96*32*1 + 255)/256, 256>>>(qkv_r, qkv_i, qkv_j, qkv_k, Wq_hi, Wq_lo, 96, 32, 1, 1);
    prepW_kernel<<<(16*96*96*9 + 255)/256, 256>>>(dw_r, dw_i, dw_j, dw_k, Wd_hi, Wd_hi, 96, 96, 9, 0);
    prepW_kernel<<<(16*32*32*1 + 255)/256, 256>>>(po_r, po_i, po_j, po_k, Wp_hi, Wp_lo, 32, 32, 1, 1);

    // 2) zero pad borders + score/norm accumulators
    borderzero_kernel<<<(BATCH*C3*BPER + 255)/256, 256>>>(Xpd);
    zeroSN_kernel<<<32, 256>>>(Sm, nq2, nk2);

    // 3) qkv 1x1 conv (2-pass A-split, reads fp32 x, writes padded fp16 hi)
    convmma_kernel<128,1,384,2,1><<<dim3(BATCH*HH, 3), 256, SMQ>>>(
        Wq_hi, Wq_lo, x, qkv_b, nullptr, Xpd, HH, WW);

    // 4) dw 3x3 conv (1-pass fp16, fp16 out)
    convmma_kernel<384,3,384,1,2><<<dim3(BATCH*HH, 3), 256, SM1>>>(
        Wd_hi, Wd_hi, Xpd, dw_b, nullptr, y2h, PXR, PXC);

    // 5) attention (norms fused into scores)
    scores_kernel<<<dim3(8, 16), 1024>>>(y2h, Sm, nq2, nk2);
    softmax_kernel<<<8, 1024>>>(Sm, nq2, nk2, temper, Am);
    av_kernel<<<dim3(8, SP/256), 256>>>(y2h, Am, aopk);

    // 6) po 1x1 conv (3-pass) -> out
    convmma_kernel<128,1,128,3,0><<<dim3(BATCH*HH, 1), 256, SM3>>>(
        Wp_hi, Wp_lo, aopk, po_b, out, nullptr, HH, WW);
}